// round 2
// baseline (speedup 1.0000x reference)
#include <cuda_runtime.h>
#include <math.h>

#define N_NODES 10000
#define N_EDGES 160000
#define NSC 128
#define NVC 64
#define LATD 64
#define EPSLN 1e-5f
#define INV_SQ3 0.57735026918962576f
#define INV_SQ2 0.70710678118654752f

// scratch: LayerNormed node features
__device__ float g_ns[N_NODES * NSC];       // 5.12 MB
__device__ float g_nv[N_NODES * NVC * 3];   // 7.68 MB

__device__ __forceinline__ float brsum(float v, volatile float* red, int t) {
#pragma unroll
    for (int o = 16; o; o >>= 1) v += __shfl_xor_sync(0xffffffffu, v, o);
    __syncthreads();
    if ((t & 31) == 0) red[t >> 5] = v;
    __syncthreads();
    return red[0] + red[1] + red[2] + red[3];
}

// ---------------------------------------------------------------------------
// Node kernel: separable LN -> g_ns/g_nv, residual (Wr_s, Wr_v) -> out
// ---------------------------------------------------------------------------
__global__ void __launch_bounds__(128, 2) node_kernel(
    const float* __restrict__ nf,
    const float* __restrict__ gsn, const float* __restrict__ bsn,
    const float* __restrict__ gvn,
    const float* __restrict__ Wrs, const float* __restrict__ Wrv,
    float* __restrict__ out)
{
    extern __shared__ float sm[];
    float* wS  = sm;             // 128*128
    float* wV  = sm + 16384;     // 64*64
    float* sb  = sm + 20480;     // 320
    float* red = sm + 20800;     // 8
    const int t = threadIdx.x;

    for (int i = t; i < 16384; i += 128) wS[i] = Wrs[i];
    for (int i = t; i < 4096;  i += 128) wV[i] = Wrv[i];
    __syncthreads();

    for (int n = blockIdx.x; n < N_NODES; n += gridDim.x) {
        const float* row = nf + n * 320;
        sb[t] = row[t];
        sb[128 + t] = row[128 + t];
        if (t < 64) sb[256 + t] = row[256 + t];
        __syncthreads();

        // scalar LN
        float x = sb[t];
        float ssum = brsum(x, red, t);
        float ssq  = brsum(x * x, red, t);
        float mu = ssum * (1.f / 128.f);
        float var = ssq * (1.f / 128.f) - mu * mu;
        float rsg = rsqrtf(var + EPSLN);
        g_ns[n * NSC + t] = (x - mu) * rsg * gsn[t] + bsn[t];

        // vector LN
        float v1 = sb[128 + t];
        float v2 = (t < 64) ? sb[256 + t] : 0.f;
        float vq = brsum(v1 * v1 + v2 * v2, red, t);
        float vsc = rsqrtf(vq * (1.f / 64.f) + EPSLN);
        g_nv[n * 192 + t] = v1 * vsc * gvn[t / 3];
        if (t < 64) g_nv[n * 192 + 128 + t] = v2 * vsc * gvn[(128 + t) / 3];

        // residual scalar: rs[t] = sum_k s[k] * Wr_s[k][t]
        float acc = 0.f;
#pragma unroll 8
        for (int k = 0; k < 128; k++) acc += sb[k] * wS[k * 128 + t];
        out[n * 320 + t] = acc;

        // residual vector: rv[f][d] = sum_c v[c][d] * Wr_v[c][f]
        {
            int f = t & 63, d = t >> 6;  // o = d*64+f, o = t covers d in {0,1}
            float a = 0.f;
#pragma unroll 8
            for (int c = 0; c < 64; c++) a += sb[128 + c * 3 + d] * wV[c * 64 + f];
            out[n * 320 + 128 + f * 3 + d] = a;
        }
        if (t < 64) {  // d = 2
            float a = 0.f;
#pragma unroll 8
            for (int c = 0; c < 64; c++) a += sb[128 + c * 3 + 2] * wV[c * 64 + t];
            out[n * 320 + 128 + t * 3 + 2] = a;
        }
        __syncthreads();
    }
}

// ---------------------------------------------------------------------------
// Edge kernel: 32 edges / block, 256 threads, fused message pipeline
// ---------------------------------------------------------------------------
// smem layout (floats)
#define OFF_S    0        // [32][256]  S = concat(ns[c], es_ln); later reused as W (env weights) stride 256
#define OFF_V    8192     // [32][384]  V = concat(nv[c], ev_ln), layout [ch][d]
#define OFF_DOT  20480    // [32][128]
#define OFF_O0   24576    // [32][192]
#define OFF_OV   30720    // [32][192]  layout [f][d]
#define OFF_T1   36864    // [32][64]
#define OFF_LAT  38912    // [32][64]
#define OFF_SH   40960    // [32][4]
#define OFF_GSE  41088
#define OFF_BSE  41216
#define OFF_GVE  41344
#define OFF_C    41408    // 32 ints
#define SMEM_EDGE_FLOATS 41440

__global__ void __launch_bounds__(256, 1) edge_kernel(
    const float* __restrict__ latents, const float* __restrict__ ef,
    const float* __restrict__ esh, const int* __restrict__ eidx,
    const int* __restrict__ act,
    const float* __restrict__ gse, const float* __restrict__ bse,
    const float* __restrict__ gve,
    const float* __restrict__ Wss0, const float* __restrict__ Wvv0,
    const float* __restrict__ Wsv1, const float* __restrict__ Wvs1,
    const float* __restrict__ Wvv1,
    const float* __restrict__ Wps,  const float* __restrict__ Wpv,
    const float* __restrict__ Wenv,
    float* __restrict__ out)
{
    extern __shared__ float sm[];
    float* sS   = sm + OFF_S;
    float* sV   = sm + OFF_V;
    float* sDot = sm + OFF_DOT;
    float* sO0  = sm + OFF_O0;
    float* sOV  = sm + OFF_OV;
    float* sT1  = sm + OFF_T1;
    float* sLat = sm + OFF_LAT;
    float* sSh  = sm + OFF_SH;
    float* pGse = sm + OFF_GSE;
    float* pBse = sm + OFF_BSE;
    float* pGve = sm + OFF_GVE;
    int*   sC   = (int*)(sm + OFF_C);

    const int t = threadIdx.x;

    if (t < 128)      { pGse[t] = gse[t]; pBse[t] = bse[t]; }
    else if (t < 192) { pGve[t - 128] = gve[t - 128]; }
    __syncthreads();

    // ---- Stage 1: load + edge LN (8 lanes per edge) ----
    {
        const int w = t >> 5, lane = t & 31;
        const int e = w * 4 + (lane >> 3), l = lane & 7;
        const int eg = blockIdx.x * 32 + e;
        const int ae = act[eg];
        const int c  = eidx[ae];
        if (l == 0) {
            sC[e] = c;
            sSh[e * 4 + 0] = esh[eg * 4 + 0];
            sSh[e * 4 + 1] = esh[eg * 4 + 1];
            sSh[e * 4 + 2] = esh[eg * 4 + 2];
            sSh[e * 4 + 3] = esh[eg * 4 + 3];
        }
        for (int i = l; i < 64;  i += 8) sLat[e * 64 + i] = latents[ae * 64 + i];
        for (int i = l; i < 128; i += 8) sS[e * 256 + i]  = g_ns[c * 128 + i];
        for (int i = l; i < 192; i += 8) sV[e * 384 + i]  = g_nv[c * 192 + i];

        // scalar LN over 128 edge scalars
        float r[16]; float sum = 0.f, ssq = 0.f;
#pragma unroll
        for (int q = 0; q < 16; q++) {
            float xv = ef[eg * 320 + q * 8 + l];
            r[q] = xv; sum += xv; ssq += xv * xv;
        }
        sum += __shfl_xor_sync(0xffffffffu, sum, 1);
        sum += __shfl_xor_sync(0xffffffffu, sum, 2);
        sum += __shfl_xor_sync(0xffffffffu, sum, 4);
        ssq += __shfl_xor_sync(0xffffffffu, ssq, 1);
        ssq += __shfl_xor_sync(0xffffffffu, ssq, 2);
        ssq += __shfl_xor_sync(0xffffffffu, ssq, 4);
        float mu  = sum * (1.f / 128.f);
        float var = ssq * (1.f / 128.f) - mu * mu;
        float rsg = rsqrtf(var + EPSLN);
#pragma unroll
        for (int q = 0; q < 16; q++) {
            int j = q * 8 + l;
            sS[e * 256 + 128 + j] = (r[q] - mu) * rsg * pGse[j] + pBse[j];
        }

        // vector LN over 64 edge vector channels
        float rv[24]; float sv2 = 0.f;
#pragma unroll
        for (int q = 0; q < 24; q++) {
            float xv = ef[eg * 320 + 128 + q * 8 + l];
            rv[q] = xv; sv2 += xv * xv;
        }
        sv2 += __shfl_xor_sync(0xffffffffu, sv2, 1);
        sv2 += __shfl_xor_sync(0xffffffffu, sv2, 2);
        sv2 += __shfl_xor_sync(0xffffffffu, sv2, 4);
        float vsc = rsqrtf(sv2 * (1.f / 64.f) + EPSLN);
#pragma unroll
        for (int q = 0; q < 24; q++) {
            int i = q * 8 + l;
            sV[e * 384 + 192 + i] = rv[q] * vsc * pGve[i / 3];
        }
    }
    __syncthreads();

    // ---- dotV = (V . sh1)/sqrt3 ----
    for (int i = t; i < 32 * 128; i += 256) {
        int e = i >> 7, cc = i & 127;
        int b = e * 384 + cc * 3;
        sDot[e * 128 + cc] =
            (sV[b] * sSh[e * 4 + 1] + sV[b + 1] * sSh[e * 4 + 2] +
             sV[b + 2] * sSh[e * 4 + 3]) * INV_SQ3;
    }
    __syncthreads();

    // ---- Stage 2: out0 = sh0*(S@Wss0) + dot@Wvv0 ----
    {
        const int jj = t & 63, egp = t >> 6;
        float accS[3][8], accD[3][8];
#pragma unroll
        for (int a = 0; a < 3; a++)
#pragma unroll
            for (int i = 0; i < 8; i++) { accS[a][i] = 0.f; accD[a][i] = 0.f; }
#pragma unroll 4
        for (int k = 0; k < 256; k++) {
            float w0 = Wss0[k * 192 + jj];
            float w1 = Wss0[k * 192 + 64 + jj];
            float w2 = Wss0[k * 192 + 128 + jj];
#pragma unroll
            for (int i = 0; i < 8; i++) {
                float a = sS[(egp * 8 + i) * 256 + k];
                accS[0][i] += a * w0; accS[1][i] += a * w1; accS[2][i] += a * w2;
            }
        }
#pragma unroll 4
        for (int k = 0; k < 128; k++) {
            float w0 = Wvv0[k * 192 + jj];
            float w1 = Wvv0[k * 192 + 64 + jj];
            float w2 = Wvv0[k * 192 + 128 + jj];
#pragma unroll
            for (int i = 0; i < 8; i++) {
                float a = sDot[(egp * 8 + i) * 128 + k];
                accD[0][i] += a * w0; accD[1][i] += a * w1; accD[2][i] += a * w2;
            }
        }
#pragma unroll
        for (int i = 0; i < 8; i++) {
            int e = egp * 8 + i;
            float s0 = sSh[e * 4];
            sO0[e * 192 + jj]       = s0 * accS[0][i] + accD[0][i];
            sO0[e * 192 + 64 + jj]  = s0 * accS[1][i] + accD[1][i];
            sO0[e * 192 + 128 + jj] = s0 * accS[2][i] + accD[2][i];
        }
    }
    __syncthreads();

    // ---- Stage 3: t1 = S @ Wsv1 ----
    {
        const int f = t & 63, egp = t >> 6;
        float acc[8];
#pragma unroll
        for (int i = 0; i < 8; i++) acc[i] = 0.f;
#pragma unroll 4
        for (int k = 0; k < 256; k++) {
            float w = Wsv1[k * 64 + f];
#pragma unroll
            for (int i = 0; i < 8; i++) acc[i] += sS[(egp * 8 + i) * 256 + k] * w;
        }
#pragma unroll
        for (int i = 0; i < 8; i++) sT1[(egp * 8 + i) * 64 + f] = acc[i];
    }
    __syncthreads();

    // ---- Stage 4: silu, env weights, vector GEMMs + epilogue ----
    // a) silu in place on first 128 cols of sO0
    for (int i = t; i < 32 * 128; i += 256) {
        int e = i >> 7, j = i & 127;
        float x = sO0[e * 192 + j];
        sO0[e * 192 + j] = x / (1.f + __expf(-x));
    }
    // b) w = lat @ Wenv -> reuse sS region (stride 256)
    {
        const int jj = t & 63, egp = t >> 6;
        float acc[3][8];
#pragma unroll
        for (int a = 0; a < 3; a++)
#pragma unroll
            for (int i = 0; i < 8; i++) acc[a][i] = 0.f;
#pragma unroll 4
        for (int k = 0; k < 64; k++) {
            float w0 = Wenv[k * 192 + jj];
            float w1 = Wenv[k * 192 + 64 + jj];
            float w2 = Wenv[k * 192 + 128 + jj];
#pragma unroll
            for (int i = 0; i < 8; i++) {
                float a = sLat[(egp * 8 + i) * 64 + k];
                acc[0][i] += a * w0; acc[1][i] += a * w1; acc[2][i] += a * w2;
            }
        }
#pragma unroll
        for (int i = 0; i < 8; i++) {
            int e = egp * 8 + i;
            sS[e * 256 + jj]       = acc[0][i];
            sS[e * 256 + 64 + jj]  = acc[1][i];
            sS[e * 256 + 128 + jj] = acc[2][i];
        }
    }
    // c) vector path: accA = V@Wvs1, accB = V@Wvv1 (cross folded into epilogue)
    {
        const int f = t & 63, egp = t >> 6;
        float aA[8][3], aB[8][3];
#pragma unroll
        for (int i = 0; i < 8; i++)
#pragma unroll
            for (int d = 0; d < 3; d++) { aA[i][d] = 0.f; aB[i][d] = 0.f; }
#pragma unroll 2
        for (int c = 0; c < 128; c++) {
            float w1 = Wvs1[c * 64 + f];
            float w2 = Wvv1[c * 64 + f];
#pragma unroll
            for (int i = 0; i < 8; i++) {
                const float* vp = &sV[(egp * 8 + i) * 384 + c * 3];
                float vx = vp[0], vy = vp[1], vz = vp[2];
                aA[i][0] += vx * w1; aA[i][1] += vy * w1; aA[i][2] += vz * w1;
                aB[i][0] += vx * w2; aB[i][1] += vy * w2; aB[i][2] += vz * w2;
            }
        }
#pragma unroll
        for (int i = 0; i < 8; i++) {
            int e = egp * 8 + i;
            float s0 = sSh[e * 4], sx = sSh[e * 4 + 1], sy = sSh[e * 4 + 2],
                  sz = sSh[e * 4 + 3];
            float t1v = sT1[e * 64 + f];
            float g = sO0[e * 192 + 128 + f];
            g = 1.f / (1.f + __expf(-g));
            float cx = (aB[i][1] * sz - aB[i][2] * sy) * INV_SQ2;
            float cy = (aB[i][2] * sx - aB[i][0] * sz) * INV_SQ2;
            float cz = (aB[i][0] * sy - aB[i][1] * sx) * INV_SQ2;
            sOV[e * 192 + f * 3 + 0] = g * (s0 * aA[i][0] + cx + t1v * sx);
            sOV[e * 192 + f * 3 + 1] = g * (s0 * aA[i][1] + cy + t1v * sy);
            sOV[e * 192 + f * 3 + 2] = g * (s0 * aA[i][2] + cz + t1v * sz);
        }
    }
    __syncthreads();

    // ---- Stage 5a: s_out = (silu_s @ Wp_s) * w[:128], scatter ----
    {
        const int jj = t & 63, egp = t >> 6;
        float a0[8], a1[8];
#pragma unroll
        for (int i = 0; i < 8; i++) { a0[i] = 0.f; a1[i] = 0.f; }
#pragma unroll 4
        for (int k = 0; k < 128; k++) {
            float wA = Wps[k * 128 + jj];
            float wB = Wps[k * 128 + 64 + jj];
#pragma unroll
            for (int i = 0; i < 8; i++) {
                float a = sO0[(egp * 8 + i) * 192 + k];
                a0[i] += a * wA; a1[i] += a * wB;
            }
        }
#pragma unroll
        for (int i = 0; i < 8; i++) {
            int e = egp * 8 + i;
            int c = sC[e];
            atomicAdd(&out[c * 320 + jj],      a0[i] * sS[e * 256 + jj] * 0.25f);
            atomicAdd(&out[c * 320 + 64 + jj], a1[i] * sS[e * 256 + 64 + jj] * 0.25f);
        }
    }
    // ---- Stage 5b: v_out = (v @ Wp_v) * w[128+f2], scatter ----
    {
        const int f2 = t & 63, egp = t >> 6;
        float av[8][3];
#pragma unroll
        for (int i = 0; i < 8; i++)
#pragma unroll
            for (int d = 0; d < 3; d++) av[i][d] = 0.f;
#pragma unroll 2
        for (int kf = 0; kf < 64; kf++) {
            float w = Wpv[kf * 64 + f2];
#pragma unroll
            for (int i = 0; i < 8; i++) {
                const float* vp = &sOV[(egp * 8 + i) * 192 + kf * 3];
                av[i][0] += vp[0] * w; av[i][1] += vp[1] * w; av[i][2] += vp[2] * w;
            }
        }
#pragma unroll
        for (int i = 0; i < 8; i++) {
            int e = egp * 8 + i;
            int c = sC[e];
            float wv = sS[e * 256 + 128 + f2] * 0.25f;
            atomicAdd(&out[c * 320 + 128 + f2 * 3 + 0], av[i][0] * wv);
            atomicAdd(&out[c * 320 + 128 + f2 * 3 + 1], av[i][1] * wv);
            atomicAdd(&out[c * 320 + 128 + f2 * 3 + 2], av[i][2] * wv);
        }
    }
}

extern "C" void kernel_launch(void* const* d_in, const int* in_sizes, int n_in,
                              void* d_out, int out_size)
{
    const float* latents = (const float*)d_in[0];
    const float* nodef   = (const float*)d_in[1];
    const float* edgef   = (const float*)d_in[2];
    const float* esh     = (const float*)d_in[3];
    const int*   eidx    = (const int*)d_in[4];
    /* d_in[5] atom_type unused */
    const int*   act     = (const int*)d_in[6];
    const float* gsn  = (const float*)d_in[7];
    const float* bsn  = (const float*)d_in[8];
    const float* gvn  = (const float*)d_in[9];
    const float* gse  = (const float*)d_in[10];
    const float* bse  = (const float*)d_in[11];
    const float* gve  = (const float*)d_in[12];
    const float* Wss0 = (const float*)d_in[13];
    const float* Wvv0 = (const float*)d_in[14];
    const float* Wsv1 = (const float*)d_in[15];
    const float* Wvs1 = (const float*)d_in[16];
    const float* Wvv1 = (const float*)d_in[17];
    const float* Wps  = (const float*)d_in[18];
    const float* Wpv  = (const float*)d_in[19];
    const float* Wenv = (const float*)d_in[20];
    const float* Wrs  = (const float*)d_in[21];
    const float* Wrv  = (const float*)d_in[22];
    float* out = (float*)d_out;

    const size_t NODE_SMEM = (16384 + 4096 + 320 + 8) * sizeof(float);
    const size_t EDGE_SMEM = SMEM_EDGE_FLOATS * sizeof(float);

    cudaFuncSetAttribute(node_kernel, cudaFuncAttributeMaxDynamicSharedMemorySize,
                         (int)NODE_SMEM);
    cudaFuncSetAttribute(edge_kernel, cudaFuncAttributeMaxDynamicSharedMemorySize,
                         (int)EDGE_SMEM);

    node_kernel<<<296, 128, NODE_SMEM>>>(nodef, gsn, bsn, gvn, Wrs, Wrv, out);
    edge_kernel<<<5000, 256, EDGE_SMEM>>>(latents, edgef, esh, eidx, act,
                                          gse, bse, gve,
                                          Wss0, Wvv0, Wsv1, Wvs1, Wvv1,
                                          Wps, Wpv, Wenv, out);
}

// round 5
// speedup vs baseline: 1.6367x; 1.6367x over previous
#include <cuda_runtime.h>
#include <math.h>

#define N_NODES 10000
#define N_EDGES 160000
#define NSC 128
#define NVC 64
#define LATD 64
#define EPSLN 1e-5f
#define INV_SQ3 0.57735026918962576f
#define INV_SQ2 0.70710678118654752f

// scratch: LayerNormed node features
__device__ float g_ns[N_NODES * NSC];       // 5.12 MB
__device__ float g_nv[N_NODES * NVC * 3];   // 7.68 MB

__device__ __forceinline__ float brsum(float v, volatile float* red, int t) {
#pragma unroll
    for (int o = 16; o; o >>= 1) v += __shfl_xor_sync(0xffffffffu, v, o);
    __syncthreads();
    if ((t & 31) == 0) red[t >> 5] = v;
    __syncthreads();
    return red[0] + red[1] + red[2] + red[3];
}

// ---------------------------------------------------------------------------
// Node kernel: separable LN -> g_ns/g_nv, residual (Wr_s, Wr_v) -> out
// ---------------------------------------------------------------------------
__global__ void __launch_bounds__(128, 2) node_kernel(
    const float* __restrict__ nf,
    const float* __restrict__ gsn, const float* __restrict__ bsn,
    const float* __restrict__ gvn,
    const float* __restrict__ Wrs, const float* __restrict__ Wrv,
    float* __restrict__ out)
{
    extern __shared__ float sm[];
    float* wS  = sm;             // 128*128
    float* wV  = sm + 16384;     // 64*64
    float* sb  = sm + 20480;     // 320
    float* red = sm + 20800;     // 8
    const int t = threadIdx.x;

    for (int i = t; i < 16384; i += 128) wS[i] = Wrs[i];
    for (int i = t; i < 4096;  i += 128) wV[i] = Wrv[i];
    __syncthreads();

    for (int n = blockIdx.x; n < N_NODES; n += gridDim.x) {
        const float* row = nf + n * 320;
        sb[t] = row[t];
        sb[128 + t] = row[128 + t];
        if (t < 64) sb[256 + t] = row[256 + t];
        __syncthreads();

        // scalar LN
        float x = sb[t];
        float ssum = brsum(x, red, t);
        float ssq  = brsum(x * x, red, t);
        float mu = ssum * (1.f / 128.f);
        float var = ssq * (1.f / 128.f) - mu * mu;
        float rsg = rsqrtf(var + EPSLN);
        g_ns[n * NSC + t] = (x - mu) * rsg * gsn[t] + bsn[t];

        // vector LN
        float v1 = sb[128 + t];
        float v2 = (t < 64) ? sb[256 + t] : 0.f;
        float vq = brsum(v1 * v1 + v2 * v2, red, t);
        float vsc = rsqrtf(vq * (1.f / 64.f) + EPSLN);
        g_nv[n * 192 + t] = v1 * vsc * gvn[t / 3];
        if (t < 64) g_nv[n * 192 + 128 + t] = v2 * vsc * gvn[(128 + t) / 3];

        // residual scalar: rs[t] = sum_k s[k] * Wr_s[k][t]
        float acc = 0.f;
#pragma unroll 8
        for (int k = 0; k < 128; k++) acc += sb[k] * wS[k * 128 + t];
        out[n * 320 + t] = acc;

        // residual vector: rv[f][d] = sum_c v[c][d] * Wr_v[c][f]
        {
            int f = t & 63, d = t >> 6;
            float a = 0.f;
#pragma unroll 8
            for (int c = 0; c < 64; c++) a += sb[128 + c * 3 + d] * wV[c * 64 + f];
            out[n * 320 + 128 + f * 3 + d] = a;
        }
        if (t < 64) {  // d = 2
            float a = 0.f;
#pragma unroll 8
            for (int c = 0; c < 64; c++) a += sb[128 + c * 3 + 2] * wV[c * 64 + t];
            out[n * 320 + 128 + t * 3 + 2] = a;
        }
        __syncthreads();
    }
}

// ---------------------------------------------------------------------------
// Edge kernel: 32 edges / block, 512 threads, fused message pipeline
// ---------------------------------------------------------------------------
// smem layout (floats)
#define OFF_S    0        // [32][256]  S = concat(ns[c], es_ln); later reused as env weights
#define OFF_V    8192     // [32][384]  V = concat(nv[c], ev_ln), layout [ch][d]
#define OFF_DOT  20480    // [32][128]
#define OFF_O0   24576    // [32][192]
#define OFF_OV   30720    // [32][192]  layout [f][d]
#define OFF_T1   36864    // [32][64]
#define OFF_LAT  38912    // [32][64]
#define OFF_SH   40960    // [32][4]
#define OFF_GSE  41088
#define OFF_BSE  41216
#define OFF_GVE  41344
#define OFF_C    41408    // 32 ints
#define SMEM_EDGE_FLOATS 41440

__global__ void __launch_bounds__(512, 1) edge_kernel(
    const float* __restrict__ latents, const float* __restrict__ ef,
    const float* __restrict__ esh, const int* __restrict__ eidx,
    const int* __restrict__ act,
    const float* __restrict__ gse, const float* __restrict__ bse,
    const float* __restrict__ gve,
    const float* __restrict__ Wss0, const float* __restrict__ Wvv0,
    const float* __restrict__ Wsv1, const float* __restrict__ Wvs1,
    const float* __restrict__ Wvv1,
    const float* __restrict__ Wps,  const float* __restrict__ Wpv,
    const float* __restrict__ Wenv,
    float* __restrict__ out)
{
    extern __shared__ float sm[];
    float* sS   = sm + OFF_S;
    float* sV   = sm + OFF_V;
    float* sDot = sm + OFF_DOT;
    float* sO0  = sm + OFF_O0;
    float* sOV  = sm + OFF_OV;
    float* sT1  = sm + OFF_T1;
    float* sLat = sm + OFF_LAT;
    float* sSh  = sm + OFF_SH;
    float* pGse = sm + OFF_GSE;
    float* pBse = sm + OFF_BSE;
    float* pGve = sm + OFF_GVE;
    int*   sC   = (int*)(sm + OFF_C);

    const int t = threadIdx.x;

    if (t < 128)      { pGse[t] = gse[t]; pBse[t] = bse[t]; }
    else if (t < 192) { pGve[t - 128] = gve[t - 128]; }
    __syncthreads();

    // ---- Stage 1: load + edge LN (16 lanes per edge, 2 edges per warp) ----
    {
        const int w = t >> 5, lane = t & 31;
        const int e = w * 2 + (lane >> 4), l = lane & 15;
        const int eg = blockIdx.x * 32 + e;
        const int ae = act[eg];
        const int c  = eidx[ae];
        if (l == 0) {
            sC[e] = c;
            sSh[e * 4 + 0] = esh[eg * 4 + 0];
            sSh[e * 4 + 1] = esh[eg * 4 + 1];
            sSh[e * 4 + 2] = esh[eg * 4 + 2];
            sSh[e * 4 + 3] = esh[eg * 4 + 3];
        }
#pragma unroll
        for (int q = 0; q < 4; q++)  sLat[e * 64 + q * 16 + l] = latents[ae * 64 + q * 16 + l];
#pragma unroll
        for (int q = 0; q < 8; q++)  sS[e * 256 + q * 16 + l]  = g_ns[c * 128 + q * 16 + l];
#pragma unroll
        for (int q = 0; q < 12; q++) sV[e * 384 + q * 16 + l]  = g_nv[c * 192 + q * 16 + l];

        // scalar LN over 128 edge scalars
        float r[8]; float sum = 0.f, ssq = 0.f;
#pragma unroll
        for (int q = 0; q < 8; q++) {
            float xv = ef[eg * 320 + q * 16 + l];
            r[q] = xv; sum += xv; ssq += xv * xv;
        }
#pragma unroll
        for (int o = 1; o < 16; o <<= 1) {
            sum += __shfl_xor_sync(0xffffffffu, sum, o);
            ssq += __shfl_xor_sync(0xffffffffu, ssq, o);
        }
        float mu  = sum * (1.f / 128.f);
        float var = ssq * (1.f / 128.f) - mu * mu;
        float rsg = rsqrtf(var + EPSLN);
#pragma unroll
        for (int q = 0; q < 8; q++) {
            int j = q * 16 + l;
            sS[e * 256 + 128 + j] = (r[q] - mu) * rsg * pGse[j] + pBse[j];
        }

        // vector LN over 64 edge vector channels
        float rv[12]; float sv2 = 0.f;
#pragma unroll
        for (int q = 0; q < 12; q++) {
            float xv = ef[eg * 320 + 128 + q * 16 + l];
            rv[q] = xv; sv2 += xv * xv;
        }
#pragma unroll
        for (int o = 1; o < 16; o <<= 1)
            sv2 += __shfl_xor_sync(0xffffffffu, sv2, o);
        float vsc = rsqrtf(sv2 * (1.f / 64.f) + EPSLN);
#pragma unroll
        for (int q = 0; q < 12; q++) {
            int i = q * 16 + l;
            sV[e * 384 + 192 + i] = rv[q] * vsc * pGve[i / 3];
        }
    }
    __syncthreads();

    // ---- dotV = (V . sh1)/sqrt3 ----
    for (int i = t; i < 32 * 128; i += 512) {
        int e = i >> 7, cc = i & 127;
        int b = e * 384 + cc * 3;
        sDot[e * 128 + cc] =
            (sV[b] * sSh[e * 4 + 1] + sV[b + 1] * sSh[e * 4 + 2] +
             sV[b + 2] * sSh[e * 4 + 3]) * INV_SQ3;
    }
    __syncthreads();

    // ---- Stage 2: out0 = sh0*(S@Wss0) + dot@Wvv0 ----
    {
        const int jj = t & 63, egp = t >> 6;   // egp in 0..7, 4 edges each
        float accS[3][4], accD[3][4];
#pragma unroll
        for (int a = 0; a < 3; a++)
#pragma unroll
            for (int i = 0; i < 4; i++) { accS[a][i] = 0.f; accD[a][i] = 0.f; }
#pragma unroll 4
        for (int k = 0; k < 256; k++) {
            float w0 = Wss0[k * 192 + jj];
            float w1 = Wss0[k * 192 + 64 + jj];
            float w2 = Wss0[k * 192 + 128 + jj];
#pragma unroll
            for (int i = 0; i < 4; i++) {
                float a = sS[(egp * 4 + i) * 256 + k];
                accS[0][i] += a * w0; accS[1][i] += a * w1; accS[2][i] += a * w2;
            }
        }
#pragma unroll 4
        for (int k = 0; k < 128; k++) {
            float w0 = Wvv0[k * 192 + jj];
            float w1 = Wvv0[k * 192 + 64 + jj];
            float w2 = Wvv0[k * 192 + 128 + jj];
#pragma unroll
            for (int i = 0; i < 4; i++) {
                float a = sDot[(egp * 4 + i) * 128 + k];
                accD[0][i] += a * w0; accD[1][i] += a * w1; accD[2][i] += a * w2;
            }
        }
#pragma unroll
        for (int i = 0; i < 4; i++) {
            int e = egp * 4 + i;
            float s0 = sSh[e * 4];
            sO0[e * 192 + jj]       = s0 * accS[0][i] + accD[0][i];
            sO0[e * 192 + 64 + jj]  = s0 * accS[1][i] + accD[1][i];
            sO0[e * 192 + 128 + jj] = s0 * accS[2][i] + accD[2][i];
        }
    }
    __syncthreads();

    // ---- Stage 3: t1 = S @ Wsv1 ----
    {
        const int f = t & 63, egp = t >> 6;
        float acc[4];
#pragma unroll
        for (int i = 0; i < 4; i++) acc[i] = 0.f;
#pragma unroll 4
        for (int k = 0; k < 256; k++) {
            float w = Wsv1[k * 64 + f];
#pragma unroll
            for (int i = 0; i < 4; i++) acc[i] += sS[(egp * 4 + i) * 256 + k] * w;
        }
#pragma unroll
        for (int i = 0; i < 4; i++) sT1[(egp * 4 + i) * 64 + f] = acc[i];
    }
    __syncthreads();

    // ---- Stage 4: silu, env weights, vector GEMMs + epilogue ----
    // a) silu in place on first 128 cols of sO0
    for (int i = t; i < 32 * 128; i += 512) {
        int e = i >> 7, j = i & 127;
        float x = sO0[e * 192 + j];
        sO0[e * 192 + j] = x / (1.f + __expf(-x));
    }
    // b) w = lat @ Wenv -> reuse sS region (stride 256)
    {
        const int jj = t & 63, egp = t >> 6;
        float acc[3][4];
#pragma unroll
        for (int a = 0; a < 3; a++)
#pragma unroll
            for (int i = 0; i < 4; i++) acc[a][i] = 0.f;
#pragma unroll 4
        for (int k = 0; k < 64; k++) {
            float w0 = Wenv[k * 192 + jj];
            float w1 = Wenv[k * 192 + 64 + jj];
            float w2 = Wenv[k * 192 + 128 + jj];
#pragma unroll
            for (int i = 0; i < 4; i++) {
                float a = sLat[(egp * 4 + i) * 64 + k];
                acc[0][i] += a * w0; acc[1][i] += a * w1; acc[2][i] += a * w2;
            }
        }
#pragma unroll
        for (int i = 0; i < 4; i++) {
            int e = egp * 4 + i;
            sS[e * 256 + jj]       = acc[0][i];
            sS[e * 256 + 64 + jj]  = acc[1][i];
            sS[e * 256 + 128 + jj] = acc[2][i];
        }
    }
    // c) vector path: accA = V@Wvs1, accB = V@Wvv1 (cross folded into epilogue)
    {
        const int f = t & 63, egp = t >> 6;
        float aA[4][3], aB[4][3];
#pragma unroll
        for (int i = 0; i < 4; i++)
#pragma unroll
            for (int d = 0; d < 3; d++) { aA[i][d] = 0.f; aB[i][d] = 0.f; }
#pragma unroll 2
        for (int c = 0; c < 128; c++) {
            float w1 = Wvs1[c * 64 + f];
            float w2 = Wvv1[c * 64 + f];
#pragma unroll
            for (int i = 0; i < 4; i++) {
                const float* vp = &sV[(egp * 4 + i) * 384 + c * 3];
                float vx = vp[0], vy = vp[1], vz = vp[2];
                aA[i][0] += vx * w1; aA[i][1] += vy * w1; aA[i][2] += vz * w1;
                aB[i][0] += vx * w2; aB[i][1] += vy * w2; aB[i][2] += vz * w2;
            }
        }
#pragma unroll
        for (int i = 0; i < 4; i++) {
            int e = egp * 4 + i;
            float s0 = sSh[e * 4], sx = sSh[e * 4 + 1], sy = sSh[e * 4 + 2],
                  sz = sSh[e * 4 + 3];
            float t1v = sT1[e * 64 + f];
            float g = sO0[e * 192 + 128 + f];
            g = 1.f / (1.f + __expf(-g));
            float cx = (aB[i][1] * sz - aB[i][2] * sy) * INV_SQ2;
            float cy = (aB[i][2] * sx - aB[i][0] * sz) * INV_SQ2;
            float cz = (aB[i][0] * sy - aB[i][1] * sx) * INV_SQ2;
            sOV[e * 192 + f * 3 + 0] = g * (s0 * aA[i][0] + cx + t1v * sx);
            sOV[e * 192 + f * 3 + 1] = g * (s0 * aA[i][1] + cy + t1v * sy);
            sOV[e * 192 + f * 3 + 2] = g * (s0 * aA[i][2] + cz + t1v * sz);
        }
    }
    __syncthreads();

    // ---- Stage 5a: s_out = (silu_s @ Wp_s) * w[:128], scatter ----
    {
        const int jj = t & 63, egp = t >> 6;
        float a0[4], a1[4];
#pragma unroll
        for (int i = 0; i < 4; i++) { a0[i] = 0.f; a1[i] = 0.f; }
#pragma unroll 4
        for (int k = 0; k < 128; k++) {
            float wA = Wps[k * 128 + jj];
            float wB = Wps[k * 128 + 64 + jj];
#pragma unroll
            for (int i = 0; i < 4; i++) {
                float a = sO0[(egp * 4 + i) * 192 + k];
                a0[i] += a * wA; a1[i] += a * wB;
            }
        }
#pragma unroll
        for (int i = 0; i < 4; i++) {
            int e = egp * 4 + i;
            int c = sC[e];
            atomicAdd(&out[c * 320 + jj],      a0[i] * sS[e * 256 + jj] * 0.25f);
            atomicAdd(&out[c * 320 + 64 + jj], a1[i] * sS[e * 256 + 64 + jj] * 0.25f);
        }
    }
    // ---- Stage 5b: v_out = (v @ Wp_v) * w[128+f2], scatter ----
    {
        const int f2 = t & 63, egp = t >> 6;
        float av[4][3];
#pragma unroll
        for (int i = 0; i < 4; i++)
#pragma unroll
            for (int d = 0; d < 3; d++) av[i][d] = 0.f;
#pragma unroll 2
        for (int kf = 0; kf < 64; kf++) {
            float w = Wpv[kf * 64 + f2];
#pragma unroll
            for (int i = 0; i < 4; i++) {
                const float* vp = &sOV[(egp * 4 + i) * 192 + kf * 3];
                av[i][0] += vp[0] * w; av[i][1] += vp[1] * w; av[i][2] += vp[2] * w;
            }
        }
#pragma unroll
        for (int i = 0; i < 4; i++) {
            int e = egp * 4 + i;
            int c = sC[e];
            float wv = sS[e * 256 + 128 + f2] * 0.25f;
            atomicAdd(&out[c * 320 + 128 + f2 * 3 + 0], av[i][0] * wv);
            atomicAdd(&out[c * 320 + 128 + f2 * 3 + 1], av[i][1] * wv);
            atomicAdd(&out[c * 320 + 128 + f2 * 3 + 2], av[i][2] * wv);
        }
    }
}

extern "C" void kernel_launch(void* const* d_in, const int* in_sizes, int n_in,
                              void* d_out, int out_size)
{
    const float* latents = (const float*)d_in[0];
    const float* nodef   = (const float*)d_in[1];
    const float* edgef   = (const float*)d_in[2];
    const float* esh     = (const float*)d_in[3];
    const int*   eidx    = (const int*)d_in[4];
    /* d_in[5] atom_type unused */
    const int*   act     = (const int*)d_in[6];
    const float* gsn  = (const float*)d_in[7];
    const float* bsn  = (const float*)d_in[8];
    const float* gvn  = (const float*)d_in[9];
    const float* gse  = (const float*)d_in[10];
    const float* bse  = (const float*)d_in[11];
    const float* gve  = (const float*)d_in[12];
    const float* Wss0 = (const float*)d_in[13];
    const float* Wvv0 = (const float*)d_in[14];
    const float* Wsv1 = (const float*)d_in[15];
    const float* Wvs1 = (const float*)d_in[16];
    const float* Wvv1 = (const float*)d_in[17];
    const float* Wps  = (const float*)d_in[18];
    const float* Wpv  = (const float*)d_in[19];
    const float* Wenv = (const float*)d_in[20];
    const float* Wrs  = (const float*)d_in[21];
    const float* Wrv  = (const float*)d_in[22];
    float* out = (float*)d_out;

    const size_t NODE_SMEM = (16384 + 4096 + 320 + 8) * sizeof(float);
    const size_t EDGE_SMEM = SMEM_EDGE_FLOATS * sizeof(float);

    cudaFuncSetAttribute(node_kernel, cudaFuncAttributeMaxDynamicSharedMemorySize,
                         (int)NODE_SMEM);
    cudaFuncSetAttribute(edge_kernel, cudaFuncAttributeMaxDynamicSharedMemorySize,
                         (int)EDGE_SMEM);

    node_kernel<<<296, 128, NODE_SMEM>>>(nodef, gsn, bsn, gvn, Wrs, Wrv, out);
    edge_kernel<<<5000, 512, EDGE_SMEM>>>(latents, edgef, esh, eidx, act,
                                          gse, bse, gve,
                                          Wss0, Wvv0, Wsv1, Wvs1, Wvv1,
                                          Wps, Wpv, Wenv, out);
}

// round 6
// speedup vs baseline: 1.6791x; 1.0259x over previous
#include <cuda_runtime.h>
#include <math.h>

#define N_NODES 10000
#define N_EDGES 160000
#define NSC 128
#define NVC 64
#define LATD 64
#define EPSLN 1e-5f
#define INV_SQ3 0.57735026918962576f
#define INV_SQ2 0.70710678118654752f

// scratch: LayerNormed node features
__device__ float g_ns[N_NODES * NSC];       // 5.12 MB
__device__ float g_nv[N_NODES * NVC * 3];   // 7.68 MB

__device__ __forceinline__ float brsum(float v, volatile float* red, int t) {
#pragma unroll
    for (int o = 16; o; o >>= 1) v += __shfl_xor_sync(0xffffffffu, v, o);
    __syncthreads();
    if ((t & 31) == 0) red[t >> 5] = v;
    __syncthreads();
    return red[0] + red[1] + red[2] + red[3];
}

// ---------------------------------------------------------------------------
// Node kernel: separable LN -> g_ns/g_nv, residual (Wr_s, Wr_v) -> out
// ---------------------------------------------------------------------------
__global__ void __launch_bounds__(128, 2) node_kernel(
    const float* __restrict__ nf,
    const float* __restrict__ gsn, const float* __restrict__ bsn,
    const float* __restrict__ gvn,
    const float* __restrict__ Wrs, const float* __restrict__ Wrv,
    float* __restrict__ out)
{
    extern __shared__ float sm[];
    float* wS  = sm;             // 128*128
    float* wV  = sm + 16384;     // 64*64
    float* sb  = sm + 20480;     // 320
    float* red = sm + 20800;     // 8
    const int t = threadIdx.x;

    for (int i = t; i < 16384; i += 128) wS[i] = Wrs[i];
    for (int i = t; i < 4096;  i += 128) wV[i] = Wrv[i];
    __syncthreads();

    for (int n = blockIdx.x; n < N_NODES; n += gridDim.x) {
        const float* row = nf + n * 320;
        sb[t] = row[t];
        sb[128 + t] = row[128 + t];
        if (t < 64) sb[256 + t] = row[256 + t];
        __syncthreads();

        float x = sb[t];
        float ssum = brsum(x, red, t);
        float ssq  = brsum(x * x, red, t);
        float mu = ssum * (1.f / 128.f);
        float var = ssq * (1.f / 128.f) - mu * mu;
        float rsg = rsqrtf(var + EPSLN);
        g_ns[n * NSC + t] = (x - mu) * rsg * gsn[t] + bsn[t];

        float v1 = sb[128 + t];
        float v2 = (t < 64) ? sb[256 + t] : 0.f;
        float vq = brsum(v1 * v1 + v2 * v2, red, t);
        float vsc = rsqrtf(vq * (1.f / 64.f) + EPSLN);
        g_nv[n * 192 + t] = v1 * vsc * gvn[t / 3];
        if (t < 64) g_nv[n * 192 + 128 + t] = v2 * vsc * gvn[(128 + t) / 3];

        float acc = 0.f;
#pragma unroll 8
        for (int k = 0; k < 128; k++) acc += sb[k] * wS[k * 128 + t];
        out[n * 320 + t] = acc;

        {
            int f = t & 63, d = t >> 6;
            float a = 0.f;
#pragma unroll 8
            for (int c = 0; c < 64; c++) a += sb[128 + c * 3 + d] * wV[c * 64 + f];
            out[n * 320 + 128 + f * 3 + d] = a;
        }
        if (t < 64) {
            float a = 0.f;
#pragma unroll 8
            for (int c = 0; c < 64; c++) a += sb[128 + c * 3 + 2] * wV[c * 64 + t];
            out[n * 320 + 128 + t * 3 + 2] = a;
        }
        __syncthreads();
    }
}

// ---------------------------------------------------------------------------
// Edge kernel: 32 edges/block, 512 threads, TRANSPOSED smem [feature][edge]
// row stride 36 floats (144B, 16B-aligned) -> broadcast LDS.128 in GEMM loops
// ---------------------------------------------------------------------------
#define ST 36
#define OFF_S    0            // [256][36]  S; rows 0..191 reused later for env w
#define OFF_V    9216         // [384][36]
#define OFF_DOT  23040        // [128][36]
#define OFF_O0   27648        // [192][36]
#define OFF_OV   34560        // [192][36]
#define OFF_T1   41472        // [64][36]
#define OFF_LAT  43776        // [64][36]
#define OFF_SH   46080        // [4][36]
#define OFF_GSE  46224
#define OFF_BSE  46352
#define OFF_GVE  46480
#define OFF_C    46544        // 32 ints
#define SMEM_EDGE_FLOATS 46576

__global__ void __launch_bounds__(512, 1) edge_kernel(
    const float* __restrict__ latents, const float* __restrict__ ef,
    const float* __restrict__ esh, const int* __restrict__ eidx,
    const int* __restrict__ act,
    const float* __restrict__ gse, const float* __restrict__ bse,
    const float* __restrict__ gve,
    const float* __restrict__ Wss0, const float* __restrict__ Wvv0,
    const float* __restrict__ Wsv1, const float* __restrict__ Wvs1,
    const float* __restrict__ Wvv1,
    const float* __restrict__ Wps,  const float* __restrict__ Wpv,
    const float* __restrict__ Wenv,
    float* __restrict__ out)
{
    extern __shared__ float sm[];
    float* sS   = sm + OFF_S;
    float* sV   = sm + OFF_V;
    float* sDot = sm + OFF_DOT;
    float* sO0  = sm + OFF_O0;
    float* sOV  = sm + OFF_OV;
    float* sT1  = sm + OFF_T1;
    float* sLat = sm + OFF_LAT;
    float* sSh  = sm + OFF_SH;
    float* pGse = sm + OFF_GSE;
    float* pBse = sm + OFF_BSE;
    float* pGve = sm + OFF_GVE;
    int*   sC   = (int*)(sm + OFF_C);

    const int t = threadIdx.x;

    if (t < 128)      { pGse[t] = gse[t]; pBse[t] = bse[t]; }
    else if (t < 192) { pGve[t - 128] = gve[t - 128]; }
    __syncthreads();

    // ---- Stage 1: load + edge LN (16 lanes/edge), float4 global loads ----
    {
        const int e = ((t >> 5) * 2) + ((t & 31) >> 4), l = t & 15;
        const int eg = blockIdx.x * 32 + e;
        const int ae = act[eg];
        const int c  = eidx[ae];
        if (l == 0) {
            sC[e] = c;
            sSh[0 * ST + e] = esh[eg * 4 + 0];
            sSh[1 * ST + e] = esh[eg * 4 + 1];
            sSh[2 * ST + e] = esh[eg * 4 + 2];
            sSh[3 * ST + e] = esh[eg * 4 + 3];
        }
        // latents: 64 floats = 16 float4
        {
            const float4* lq = (const float4*)(latents + (size_t)ae * 64);
            float4 v = lq[l];
            sLat[(4 * l + 0) * ST + e] = v.x;
            sLat[(4 * l + 1) * ST + e] = v.y;
            sLat[(4 * l + 2) * ST + e] = v.z;
            sLat[(4 * l + 3) * ST + e] = v.w;
        }
        // node scalars: 128 floats = 32 float4
        {
            const float4* nq = (const float4*)(g_ns + (size_t)c * 128);
            float4 a = nq[l], b = nq[l + 16];
#pragma unroll
            for (int s = 0; s < 4; s++) {
                sS[(4 * l + s) * ST + e]      = ((const float*)&a)[s];
                sS[(64 + 4 * l + s) * ST + e] = ((const float*)&b)[s];
            }
        }
        // node vectors: 192 floats = 48 float4
        {
            const float4* nq = (const float4*)(g_nv + (size_t)c * 192);
            float4 a = nq[l], b = nq[l + 16], cc4 = nq[l + 32];
#pragma unroll
            for (int s = 0; s < 4; s++) {
                sV[(4 * l + s) * ST + e]       = ((const float*)&a)[s];
                sV[(64 + 4 * l + s) * ST + e]  = ((const float*)&b)[s];
                sV[(128 + 4 * l + s) * ST + e] = ((const float*)&cc4)[s];
            }
        }
        const float4* eq = (const float4*)(ef + (size_t)eg * 320);
        // edge scalar LN
        float4 ra = eq[l], rb = eq[l + 16];
        float sum = ra.x + ra.y + ra.z + ra.w + rb.x + rb.y + rb.z + rb.w;
        float ssq = ra.x*ra.x + ra.y*ra.y + ra.z*ra.z + ra.w*ra.w
                  + rb.x*rb.x + rb.y*rb.y + rb.z*rb.z + rb.w*rb.w;
#pragma unroll
        for (int o = 1; o < 16; o <<= 1) {
            sum += __shfl_xor_sync(0xffffffffu, sum, o);
            ssq += __shfl_xor_sync(0xffffffffu, ssq, o);
        }
        float mu  = sum * (1.f / 128.f);
        float var = ssq * (1.f / 128.f) - mu * mu;
        float rsg = rsqrtf(var + EPSLN);
#pragma unroll
        for (int s = 0; s < 4; s++) {
            int j0 = 4 * l + s, j1 = 64 + 4 * l + s;
            sS[(128 + j0) * ST + e] = (((const float*)&ra)[s] - mu) * rsg * pGse[j0] + pBse[j0];
            sS[(128 + j1) * ST + e] = (((const float*)&rb)[s] - mu) * rsg * pGse[j1] + pBse[j1];
        }
        // edge vector LN
        float4 va = eq[32 + l], vb = eq[48 + l], vc = eq[64 + l];
        float sv2 = va.x*va.x + va.y*va.y + va.z*va.z + va.w*va.w
                  + vb.x*vb.x + vb.y*vb.y + vb.z*vb.z + vb.w*vb.w
                  + vc.x*vc.x + vc.y*vc.y + vc.z*vc.z + vc.w*vc.w;
#pragma unroll
        for (int o = 1; o < 16; o <<= 1)
            sv2 += __shfl_xor_sync(0xffffffffu, sv2, o);
        float vsc = rsqrtf(sv2 * (1.f / 64.f) + EPSLN);
#pragma unroll
        for (int s = 0; s < 4; s++) {
            int i0 = 4 * l + s, i1 = 64 + 4 * l + s, i2 = 128 + 4 * l + s;
            sV[(192 + i0) * ST + e] = ((const float*)&va)[s] * vsc * pGve[i0 / 3];
            sV[(192 + i1) * ST + e] = ((const float*)&vb)[s] * vsc * pGve[i1 / 3];
            sV[(192 + i2) * ST + e] = ((const float*)&vc)[s] * vsc * pGve[i2 / 3];
        }
    }
    __syncthreads();

    // ---- dotV = (V . sh1)/sqrt3 ; stride-1 across lanes ----
    {
        const int e = t & 31;
        float shx = sSh[1 * ST + e], shy = sSh[2 * ST + e], shz = sSh[3 * ST + e];
#pragma unroll
        for (int it = 0; it < 8; it++) {
            int cc = (t >> 5) + 16 * it;
            sDot[cc * ST + e] =
                (sV[(cc * 3 + 0) * ST + e] * shx +
                 sV[(cc * 3 + 1) * ST + e] * shy +
                 sV[(cc * 3 + 2) * ST + e] * shz) * INV_SQ3;
        }
    }
    __syncthreads();

    const float4* sS4   = (const float4*)sS;
    const float4* sD4   = (const float4*)sDot;
    const float4* sL4   = (const float4*)sLat;
    const float4* sV4   = (const float4*)sV;
    const float4* sO04  = (const float4*)sO0;
    const float4* sOV4  = (const float4*)sOV;
    const int NQ = ST / 4;  // 9 float4 per row

    // ---- Stage 2: out0 = sh0*(S@Wss0) + dot@Wvv0 ----
    {
        const int jj = t & 63, egp = t >> 6;
        float4 aS0 = {0,0,0,0}, aS1 = {0,0,0,0}, aS2 = {0,0,0,0};
        float4 aD0 = {0,0,0,0}, aD1 = {0,0,0,0}, aD2 = {0,0,0,0};
#pragma unroll 4
        for (int k = 0; k < 256; k++) {
            float4 a = sS4[k * NQ + egp];
            float w0 = Wss0[k * 192 + jj];
            float w1 = Wss0[k * 192 + 64 + jj];
            float w2 = Wss0[k * 192 + 128 + jj];
            aS0.x += a.x*w0; aS0.y += a.y*w0; aS0.z += a.z*w0; aS0.w += a.w*w0;
            aS1.x += a.x*w1; aS1.y += a.y*w1; aS1.z += a.z*w1; aS1.w += a.w*w1;
            aS2.x += a.x*w2; aS2.y += a.y*w2; aS2.z += a.z*w2; aS2.w += a.w*w2;
        }
#pragma unroll 4
        for (int k = 0; k < 128; k++) {
            float4 a = sD4[k * NQ + egp];
            float w0 = Wvv0[k * 192 + jj];
            float w1 = Wvv0[k * 192 + 64 + jj];
            float w2 = Wvv0[k * 192 + 128 + jj];
            aD0.x += a.x*w0; aD0.y += a.y*w0; aD0.z += a.z*w0; aD0.w += a.w*w0;
            aD1.x += a.x*w1; aD1.y += a.y*w1; aD1.z += a.z*w1; aD1.w += a.w*w1;
            aD2.x += a.x*w2; aD2.y += a.y*w2; aD2.z += a.z*w2; aD2.w += a.w*w2;
        }
        float4 s0 = *(const float4*)&sSh[0 * ST + egp * 4];
        float4 o0, o1, o2;
        o0.x = s0.x*aS0.x + aD0.x; o0.y = s0.y*aS0.y + aD0.y;
        o0.z = s0.z*aS0.z + aD0.z; o0.w = s0.w*aS0.w + aD0.w;
        o1.x = s0.x*aS1.x + aD1.x; o1.y = s0.y*aS1.y + aD1.y;
        o1.z = s0.z*aS1.z + aD1.z; o1.w = s0.w*aS1.w + aD1.w;
        o2.x = s0.x*aS2.x + aD2.x; o2.y = s0.y*aS2.y + aD2.y;
        o2.z = s0.z*aS2.z + aD2.z; o2.w = s0.w*aS2.w + aD2.w;
        *(float4*)&sO0[jj * ST + egp * 4]         = o0;
        *(float4*)&sO0[(jj + 64) * ST + egp * 4]  = o1;
        *(float4*)&sO0[(jj + 128) * ST + egp * 4] = o2;
    }
    __syncthreads();

    // ---- Stage 3: t1 = S @ Wsv1 ----
    {
        const int f = t & 63, egp = t >> 6;
        float4 acc = {0,0,0,0};
#pragma unroll 4
        for (int k = 0; k < 256; k++) {
            float4 a = sS4[k * NQ + egp];
            float w = Wsv1[k * 64 + f];
            acc.x += a.x*w; acc.y += a.y*w; acc.z += a.z*w; acc.w += a.w*w;
        }
        *(float4*)&sT1[f * ST + egp * 4] = acc;
    }
    __syncthreads();

    // ---- Stage 4a: silu in place on rows 0..127 of sO0 ----
    {
        const int e = t & 31;
#pragma unroll
        for (int it = 0; it < 8; it++) {
            int j = (t >> 5) + 16 * it;
            float x = sO0[j * ST + e];
            sO0[j * ST + e] = x / (1.f + __expf(-x));
        }
    }
    // ---- Stage 4b: w = lat @ Wenv -> sS rows 0..191 ----
    {
        const int jj = t & 63, egp = t >> 6;
        float4 a0 = {0,0,0,0}, a1 = {0,0,0,0}, a2 = {0,0,0,0};
#pragma unroll 4
        for (int k = 0; k < 64; k++) {
            float4 a = sL4[k * NQ + egp];
            float w0 = Wenv[k * 192 + jj];
            float w1 = Wenv[k * 192 + 64 + jj];
            float w2 = Wenv[k * 192 + 128 + jj];
            a0.x += a.x*w0; a0.y += a.y*w0; a0.z += a.z*w0; a0.w += a.w*w0;
            a1.x += a.x*w1; a1.y += a.y*w1; a1.z += a.z*w1; a1.w += a.w*w1;
            a2.x += a.x*w2; a2.y += a.y*w2; a2.z += a.z*w2; a2.w += a.w*w2;
        }
        __syncthreads();   // all reads of sS (stage 3) done before overwrite
        *(float4*)&sS[jj * ST + egp * 4]         = a0;
        *(float4*)&sS[(jj + 64) * ST + egp * 4]  = a1;
        *(float4*)&sS[(jj + 128) * ST + egp * 4] = a2;
    }
    // ---- Stage 4c: vector path (cross folded) ----
    {
        const int f = t & 63, egp = t >> 6;
        float4 aAx={0,0,0,0}, aAy={0,0,0,0}, aAz={0,0,0,0};
        float4 aBx={0,0,0,0}, aBy={0,0,0,0}, aBz={0,0,0,0};
#pragma unroll 2
        for (int c = 0; c < 128; c++) {
            float4 vx = sV4[(c * 3 + 0) * NQ + egp];
            float4 vy = sV4[(c * 3 + 1) * NQ + egp];
            float4 vz = sV4[(c * 3 + 2) * NQ + egp];
            float w1 = Wvs1[c * 64 + f];
            float w2 = Wvv1[c * 64 + f];
            aAx.x += vx.x*w1; aAx.y += vx.y*w1; aAx.z += vx.z*w1; aAx.w += vx.w*w1;
            aAy.x += vy.x*w1; aAy.y += vy.y*w1; aAy.z += vy.z*w1; aAy.w += vy.w*w1;
            aAz.x += vz.x*w1; aAz.y += vz.y*w1; aAz.z += vz.z*w1; aAz.w += vz.w*w1;
            aBx.x += vx.x*w2; aBx.y += vx.y*w2; aBx.z += vx.z*w2; aBx.w += vx.w*w2;
            aBy.x += vy.x*w2; aBy.y += vy.y*w2; aBy.z += vy.z*w2; aBy.w += vy.w*w2;
            aBz.x += vz.x*w2; aBz.y += vz.y*w2; aBz.z += vz.z*w2; aBz.w += vz.w*w2;
        }
        float4 s0 = *(const float4*)&sSh[0 * ST + egp * 4];
        float4 sx = *(const float4*)&sSh[1 * ST + egp * 4];
        float4 sy = *(const float4*)&sSh[2 * ST + egp * 4];
        float4 sz = *(const float4*)&sSh[3 * ST + egp * 4];
        float4 t1 = *(const float4*)&sT1[f * ST + egp * 4];
        float4 gg = *(const float4*)&sO0[(128 + f) * ST + egp * 4];
        float4 ox, oy, oz;
#pragma unroll
        for (int s = 0; s < 4; s++) {
            float g = 1.f / (1.f + __expf(-((const float*)&gg)[s]));
            float bx = ((const float*)&aBx)[s], by = ((const float*)&aBy)[s],
                  bz = ((const float*)&aBz)[s];
            float cx = (by * ((const float*)&sz)[s] - bz * ((const float*)&sy)[s]) * INV_SQ2;
            float cy = (bz * ((const float*)&sx)[s] - bx * ((const float*)&sz)[s]) * INV_SQ2;
            float cz = (bx * ((const float*)&sy)[s] - by * ((const float*)&sx)[s]) * INV_SQ2;
            float t1v = ((const float*)&t1)[s];
            ((float*)&ox)[s] = g * (((const float*)&s0)[s] * ((const float*)&aAx)[s] + cx + t1v * ((const float*)&sx)[s]);
            ((float*)&oy)[s] = g * (((const float*)&s0)[s] * ((const float*)&aAy)[s] + cy + t1v * ((const float*)&sy)[s]);
            ((float*)&oz)[s] = g * (((const float*)&s0)[s] * ((const float*)&aAz)[s] + cz + t1v * ((const float*)&sz)[s]);
        }
        *(float4*)&sOV[(f * 3 + 0) * ST + egp * 4] = ox;
        *(float4*)&sOV[(f * 3 + 1) * ST + egp * 4] = oy;
        *(float4*)&sOV[(f * 3 + 2) * ST + egp * 4] = oz;
    }
    __syncthreads();

    // ---- Stage 5a: s_out = (silu_s @ Wp_s) * w[:128], scatter ----
    {
        const int jj = t & 63, egp = t >> 6;
        float4 a0 = {0,0,0,0}, a1 = {0,0,0,0};
#pragma unroll 4
        for (int k = 0; k < 128; k++) {
            float4 a = sO04[k * NQ + egp];
            float wA = Wps[k * 128 + jj];
            float wB = Wps[k * 128 + 64 + jj];
            a0.x += a.x*wA; a0.y += a.y*wA; a0.z += a.z*wA; a0.w += a.w*wA;
            a1.x += a.x*wB; a1.y += a.y*wB; a1.z += a.z*wB; a1.w += a.w*wB;
        }
        float4 w0 = *(const float4*)&sS[jj * ST + egp * 4];
        float4 w1 = *(const float4*)&sS[(jj + 64) * ST + egp * 4];
#pragma unroll
        for (int s = 0; s < 4; s++) {
            int c = sC[egp * 4 + s];
            atomicAdd(&out[c * 320 + jj],
                      ((const float*)&a0)[s] * ((const float*)&w0)[s] * 0.25f);
            atomicAdd(&out[c * 320 + 64 + jj],
                      ((const float*)&a1)[s] * ((const float*)&w1)[s] * 0.25f);
        }
    }
    // ---- Stage 5b: v_out = (v @ Wp_v) * w[128+f2], scatter ----
    {
        const int f2 = t & 63, egp = t >> 6;
        float4 avx = {0,0,0,0}, avy = {0,0,0,0}, avz = {0,0,0,0};
#pragma unroll 2
        for (int kf = 0; kf < 64; kf++) {
            float4 vx = sOV4[(kf * 3 + 0) * NQ + egp];
            float4 vy = sOV4[(kf * 3 + 1) * NQ + egp];
            float4 vz = sOV4[(kf * 3 + 2) * NQ + egp];
            float w = Wpv[kf * 64 + f2];
            avx.x += vx.x*w; avx.y += vx.y*w; avx.z += vx.z*w; avx.w += vx.w*w;
            avy.x += vy.x*w; avy.y += vy.y*w; avy.z += vy.z*w; avy.w += vy.w*w;
            avz.x += vz.x*w; avz.y += vz.y*w; avz.z += vz.z*w; avz.w += vz.w*w;
        }
        float4 wv = *(const float4*)&sS[(128 + f2) * ST + egp * 4];
#pragma unroll
        for (int s = 0; s < 4; s++) {
            int c = sC[egp * 4 + s];
            float ww = ((const float*)&wv)[s] * 0.25f;
            atomicAdd(&out[c * 320 + 128 + f2 * 3 + 0], ((const float*)&avx)[s] * ww);
            atomicAdd(&out[c * 320 + 128 + f2 * 3 + 1], ((const float*)&avy)[s] * ww);
            atomicAdd(&out[c * 320 + 128 + f2 * 3 + 2], ((const float*)&avz)[s] * ww);
        }
    }
}

extern "C" void kernel_launch(void* const* d_in, const int* in_sizes, int n_in,
                              void* d_out, int out_size)
{
    const float* latents = (const float*)d_in[0];
    const float* nodef   = (const float*)d_in[1];
    const float* edgef   = (const float*)d_in[2];
    const float* esh     = (const float*)d_in[3];
    const int*   eidx    = (const int*)d_in[4];
    /* d_in[5] atom_type unused */
    const int*   act     = (const int*)d_in[6];
    const float* gsn  = (const float*)d_in[7];
    const float* bsn  = (const float*)d_in[8];
    const float* gvn  = (const float*)d_in[9];
    const float* gse  = (const float*)d_in[10];
    const float* bse  = (const float*)d_in[11];
    const float* gve  = (const float*)d_in[12];
    const float* Wss0 = (const float*)d_in[13];
    const float* Wvv0 = (const float*)d_in[14];
    const float* Wsv1 = (const float*)d_in[15];
    const float* Wvs1 = (const float*)d_in[16];
    const float* Wvv1 = (const float*)d_in[17];
    const float* Wps  = (const float*)d_in[18];
    const float* Wpv  = (const float*)d_in[19];
    const float* Wenv = (const float*)d_in[20];
    const float* Wrs  = (const float*)d_in[21];
    const float* Wrv  = (const float*)d_in[22];
    float* out = (float*)d_out;

    const size_t NODE_SMEM = (16384 + 4096 + 320 + 8) * sizeof(float);
    const size_t EDGE_SMEM = SMEM_EDGE_FLOATS * sizeof(float);

    cudaFuncSetAttribute(node_kernel, cudaFuncAttributeMaxDynamicSharedMemorySize,
                         (int)NODE_SMEM);
    cudaFuncSetAttribute(edge_kernel, cudaFuncAttributeMaxDynamicSharedMemorySize,
                         (int)EDGE_SMEM);

    node_kernel<<<296, 128, NODE_SMEM>>>(nodef, gsn, bsn, gvn, Wrs, Wrv, out);
    edge_kernel<<<5000, 512, EDGE_SMEM>>>(latents, edgef, esh, eidx, act,
                                          gse, bse, gve,
                                          Wss0, Wvv0, Wsv1, Wvs1, Wvv1,
                                          Wps, Wpv, Wenv, out);
}

// round 7
// speedup vs baseline: 1.8881x; 1.1245x over previous
#include <cuda_runtime.h>
#include <math.h>

#define N_NODES 10000
#define N_EDGES 160000
#define NSC 128
#define NVC 64
#define LATD 64
#define EPSLN 1e-5f
#define INV_SQ3 0.57735026918962576f
#define INV_SQ2 0.70710678118654752f

typedef unsigned long long u64;

// packed f32x2 helpers (FFMA2 path — only reachable via PTX)
__device__ __forceinline__ u64 pk2(float w) {
    u64 r; asm("mov.b64 %0, {%1, %1};" : "=l"(r) : "f"(w)); return r;
}
__device__ __forceinline__ void fma2(u64& acc, u64 a, u64 b) {
    asm("fma.rn.f32x2 %0, %1, %2, %0;" : "+l"(acc) : "l"(a), "l"(b));
}
__device__ __forceinline__ float2 up(u64 v) {
    union { u64 u; float2 f; } x; x.u = v; return x.f;
}
__device__ __forceinline__ void un4(const u64* p, float* f) {
    float2 a = up(p[0]), b = up(p[1]);
    f[0] = a.x; f[1] = a.y; f[2] = b.x; f[3] = b.y;
}

// scratch: LayerNormed node features
__device__ float g_ns[N_NODES * NSC];       // 5.12 MB
__device__ float g_nv[N_NODES * NVC * 3];   // 7.68 MB

__device__ __forceinline__ float brsum(float v, volatile float* red, int t) {
#pragma unroll
    for (int o = 16; o; o >>= 1) v += __shfl_xor_sync(0xffffffffu, v, o);
    __syncthreads();
    if ((t & 31) == 0) red[t >> 5] = v;
    __syncthreads();
    return red[0] + red[1] + red[2] + red[3];
}

// ---------------------------------------------------------------------------
// Node kernel: separable LN -> g_ns/g_nv, residual (Wr_s, Wr_v) -> out
// ---------------------------------------------------------------------------
__global__ void __launch_bounds__(128, 2) node_kernel(
    const float* __restrict__ nf,
    const float* __restrict__ gsn, const float* __restrict__ bsn,
    const float* __restrict__ gvn,
    const float* __restrict__ Wrs, const float* __restrict__ Wrv,
    float* __restrict__ out)
{
    extern __shared__ float sm[];
    float* wS  = sm;             // 128*128
    float* wV  = sm + 16384;     // 64*64
    float* sb  = sm + 20480;     // 320
    float* red = sm + 20800;     // 8
    const int t = threadIdx.x;

    for (int i = t; i < 16384; i += 128) wS[i] = Wrs[i];
    for (int i = t; i < 4096;  i += 128) wV[i] = Wrv[i];
    __syncthreads();

    for (int n = blockIdx.x; n < N_NODES; n += gridDim.x) {
        const float* row = nf + n * 320;
        sb[t] = row[t];
        sb[128 + t] = row[128 + t];
        if (t < 64) sb[256 + t] = row[256 + t];
        __syncthreads();

        float x = sb[t];
        float ssum = brsum(x, red, t);
        float ssq  = brsum(x * x, red, t);
        float mu = ssum * (1.f / 128.f);
        float var = ssq * (1.f / 128.f) - mu * mu;
        float rsg = rsqrtf(var + EPSLN);
        g_ns[n * NSC + t] = (x - mu) * rsg * gsn[t] + bsn[t];

        float v1 = sb[128 + t];
        float v2 = (t < 64) ? sb[256 + t] : 0.f;
        float vq = brsum(v1 * v1 + v2 * v2, red, t);
        float vsc = rsqrtf(vq * (1.f / 64.f) + EPSLN);
        g_nv[n * 192 + t] = v1 * vsc * gvn[t / 3];
        if (t < 64) g_nv[n * 192 + 128 + t] = v2 * vsc * gvn[(128 + t) / 3];

        float acc = 0.f;
#pragma unroll 8
        for (int k = 0; k < 128; k++) acc += sb[k] * wS[k * 128 + t];
        out[n * 320 + t] = acc;

        {
            int f = t & 63, d = t >> 6;
            float a = 0.f;
#pragma unroll 8
            for (int c = 0; c < 64; c++) a += sb[128 + c * 3 + d] * wV[c * 64 + f];
            out[n * 320 + 128 + f * 3 + d] = a;
        }
        if (t < 64) {
            float a = 0.f;
#pragma unroll 8
            for (int c = 0; c < 64; c++) a += sb[128 + c * 3 + 2] * wV[c * 64 + t];
            out[n * 320 + 128 + t * 3 + 2] = a;
        }
        __syncthreads();
    }
}

// ---------------------------------------------------------------------------
// Edge kernel: 16 edges/block, 256 threads, 2 CTAs/SM, packed-f32x2 GEMMs
// smem transposed [feature][edge], row stride ST=20 floats (80B, 16B-aligned)
// ---------------------------------------------------------------------------
#define ST 20
#define NQ2 5                  // ulonglong2 (16B) per row
#define OFF_S    0             // [256][20]
#define OFF_V    5120          // [384][20]
#define OFF_DOT  12800         // [128][20]
#define OFF_O0   15360         // [192][20]
#define OFF_OV   19200         // [192][20]
#define OFF_T1   23040         // [64][20]
#define OFF_LAT  24320         // [64][20]
#define OFF_SH   25600         // [4][20]
#define OFF_GSE  25680
#define OFF_BSE  25808
#define OFF_GVE  25936
#define OFF_C    26000         // 16 ints
#define SMEM_EDGE_FLOATS 26016

__global__ void __launch_bounds__(256, 2) edge_kernel(
    const float* __restrict__ latents, const float* __restrict__ ef,
    const float* __restrict__ esh, const int* __restrict__ eidx,
    const int* __restrict__ act,
    const float* __restrict__ gse, const float* __restrict__ bse,
    const float* __restrict__ gve,
    const float* __restrict__ Wss0, const float* __restrict__ Wvv0,
    const float* __restrict__ Wsv1, const float* __restrict__ Wvs1,
    const float* __restrict__ Wvv1,
    const float* __restrict__ Wps,  const float* __restrict__ Wpv,
    const float* __restrict__ Wenv,
    float* __restrict__ out)
{
    extern __shared__ float sm[];
    float* sS   = sm + OFF_S;
    float* sV   = sm + OFF_V;
    float* sDot = sm + OFF_DOT;
    float* sO0  = sm + OFF_O0;
    float* sOV  = sm + OFF_OV;
    float* sT1  = sm + OFF_T1;
    float* sLat = sm + OFF_LAT;
    float* sSh  = sm + OFF_SH;
    float* pGse = sm + OFF_GSE;
    float* pBse = sm + OFF_BSE;
    float* pGve = sm + OFF_GVE;
    int*   sC   = (int*)(sm + OFF_C);

    const int t = threadIdx.x;

    if (t < 128) { pGse[t] = gse[t]; pBse[t] = bse[t]; }
    else if (t < 192) { pGve[t - 128] = gve[t - 128]; }
    __syncthreads();

    // ---- Stage 1: load + edge LN (16 lanes/edge), float4 global loads ----
    {
        const int e = ((t >> 5) * 2) + ((t & 31) >> 4), l = t & 15;
        const int eg = blockIdx.x * 16 + e;
        const int ae = act[eg];
        const int c  = eidx[ae];
        if (l == 0) {
            sC[e] = c;
            sSh[0 * ST + e] = esh[eg * 4 + 0];
            sSh[1 * ST + e] = esh[eg * 4 + 1];
            sSh[2 * ST + e] = esh[eg * 4 + 2];
            sSh[3 * ST + e] = esh[eg * 4 + 3];
        }
        {
            const float4* lq = (const float4*)(latents + (size_t)ae * 64);
            float4 v = lq[l];
            sLat[(4 * l + 0) * ST + e] = v.x;
            sLat[(4 * l + 1) * ST + e] = v.y;
            sLat[(4 * l + 2) * ST + e] = v.z;
            sLat[(4 * l + 3) * ST + e] = v.w;
        }
        {
            const float4* nq = (const float4*)(g_ns + (size_t)c * 128);
            float4 a = nq[l], b = nq[l + 16];
#pragma unroll
            for (int s = 0; s < 4; s++) {
                sS[(4 * l + s) * ST + e]      = ((const float*)&a)[s];
                sS[(64 + 4 * l + s) * ST + e] = ((const float*)&b)[s];
            }
        }
        {
            const float4* nq = (const float4*)(g_nv + (size_t)c * 192);
            float4 a = nq[l], b = nq[l + 16], cc4 = nq[l + 32];
#pragma unroll
            for (int s = 0; s < 4; s++) {
                sV[(4 * l + s) * ST + e]       = ((const float*)&a)[s];
                sV[(64 + 4 * l + s) * ST + e]  = ((const float*)&b)[s];
                sV[(128 + 4 * l + s) * ST + e] = ((const float*)&cc4)[s];
            }
        }
        const float4* eq = (const float4*)(ef + (size_t)eg * 320);
        float4 ra = eq[l], rb = eq[l + 16];
        float sum = ra.x + ra.y + ra.z + ra.w + rb.x + rb.y + rb.z + rb.w;
        float ssq = ra.x*ra.x + ra.y*ra.y + ra.z*ra.z + ra.w*ra.w
                  + rb.x*rb.x + rb.y*rb.y + rb.z*rb.z + rb.w*rb.w;
#pragma unroll
        for (int o = 1; o < 16; o <<= 1) {
            sum += __shfl_xor_sync(0xffffffffu, sum, o);
            ssq += __shfl_xor_sync(0xffffffffu, ssq, o);
        }
        float mu  = sum * (1.f / 128.f);
        float var = ssq * (1.f / 128.f) - mu * mu;
        float rsg = rsqrtf(var + EPSLN);
#pragma unroll
        for (int s = 0; s < 4; s++) {
            int j0 = 4 * l + s, j1 = 64 + 4 * l + s;
            sS[(128 + j0) * ST + e] = (((const float*)&ra)[s] - mu) * rsg * pGse[j0] + pBse[j0];
            sS[(128 + j1) * ST + e] = (((const float*)&rb)[s] - mu) * rsg * pGse[j1] + pBse[j1];
        }
        float4 va = eq[32 + l], vb = eq[48 + l], vc = eq[64 + l];
        float sv2 = va.x*va.x + va.y*va.y + va.z*va.z + va.w*va.w
                  + vb.x*vb.x + vb.y*vb.y + vb.z*vb.z + vb.w*vb.w
                  + vc.x*vc.x + vc.y*vc.y + vc.z*vc.z + vc.w*vc.w;
#pragma unroll
        for (int o = 1; o < 16; o <<= 1)
            sv2 += __shfl_xor_sync(0xffffffffu, sv2, o);
        float vsc = rsqrtf(sv2 * (1.f / 64.f) + EPSLN);
#pragma unroll
        for (int s = 0; s < 4; s++) {
            int i0 = 4 * l + s, i1 = 64 + 4 * l + s, i2 = 128 + 4 * l + s;
            sV[(192 + i0) * ST + e] = ((const float*)&va)[s] * vsc * pGve[i0 / 3];
            sV[(192 + i1) * ST + e] = ((const float*)&vb)[s] * vsc * pGve[i1 / 3];
            sV[(192 + i2) * ST + e] = ((const float*)&vc)[s] * vsc * pGve[i2 / 3];
        }
    }
    __syncthreads();

    // ---- dotV = (V . sh1)/sqrt3 ----
    {
        const int e = t & 15;
        float shx = sSh[1 * ST + e], shy = sSh[2 * ST + e], shz = sSh[3 * ST + e];
#pragma unroll
        for (int it = 0; it < 8; it++) {
            int cc = (t >> 4) + 16 * it;
            sDot[cc * ST + e] =
                (sV[(cc * 3 + 0) * ST + e] * shx +
                 sV[(cc * 3 + 1) * ST + e] * shy +
                 sV[(cc * 3 + 2) * ST + e] * shz) * INV_SQ3;
        }
    }
    __syncthreads();

    const ulonglong2* sS2  = (const ulonglong2*)sS;
    const ulonglong2* sD2  = (const ulonglong2*)sDot;
    const ulonglong2* sL2  = (const ulonglong2*)sLat;
    const ulonglong2* sV2  = (const ulonglong2*)sV;
    const ulonglong2* sO02 = (const ulonglong2*)sO0;
    const ulonglong2* sOV2 = (const ulonglong2*)sOV;

    // ---- Stage 2: out0 = sh0*(S@Wss0) + dot@Wvv0 ----
    {
        const int jj = t & 63, egp = t >> 6;
        u64 aS[3][2] = {{0,0},{0,0},{0,0}};
        u64 aD[3][2] = {{0,0},{0,0},{0,0}};
#pragma unroll 4
        for (int k = 0; k < 256; k++) {
            ulonglong2 a = sS2[k * NQ2 + egp];
            u64 W0 = pk2(Wss0[k * 192 + jj]);
            u64 W1 = pk2(Wss0[k * 192 + 64 + jj]);
            u64 W2 = pk2(Wss0[k * 192 + 128 + jj]);
            fma2(aS[0][0], a.x, W0); fma2(aS[0][1], a.y, W0);
            fma2(aS[1][0], a.x, W1); fma2(aS[1][1], a.y, W1);
            fma2(aS[2][0], a.x, W2); fma2(aS[2][1], a.y, W2);
        }
#pragma unroll 4
        for (int k = 0; k < 128; k++) {
            ulonglong2 a = sD2[k * NQ2 + egp];
            u64 W0 = pk2(Wvv0[k * 192 + jj]);
            u64 W1 = pk2(Wvv0[k * 192 + 64 + jj]);
            u64 W2 = pk2(Wvv0[k * 192 + 128 + jj]);
            fma2(aD[0][0], a.x, W0); fma2(aD[0][1], a.y, W0);
            fma2(aD[1][0], a.x, W1); fma2(aD[1][1], a.y, W1);
            fma2(aD[2][0], a.x, W2); fma2(aD[2][1], a.y, W2);
        }
        float4 s0 = *(const float4*)&sSh[0 * ST + egp * 4];
        float S0[4], S1[4], S2[4], D0[4], D1[4], D2[4];
        un4(aS[0], S0); un4(aS[1], S1); un4(aS[2], S2);
        un4(aD[0], D0); un4(aD[1], D1); un4(aD[2], D2);
        float4 o0, o1, o2;
#pragma unroll
        for (int s = 0; s < 4; s++) {
            float sv = ((const float*)&s0)[s];
            ((float*)&o0)[s] = sv * S0[s] + D0[s];
            ((float*)&o1)[s] = sv * S1[s] + D1[s];
            ((float*)&o2)[s] = sv * S2[s] + D2[s];
        }
        *(float4*)&sO0[jj * ST + egp * 4]         = o0;
        *(float4*)&sO0[(jj + 64) * ST + egp * 4]  = o1;
        *(float4*)&sO0[(jj + 128) * ST + egp * 4] = o2;
    }
    __syncthreads();

    // ---- Stage 3: t1 = S @ Wsv1 ----
    {
        const int f = t & 63, egp = t >> 6;
        u64 acc[2] = {0, 0};
#pragma unroll 4
        for (int k = 0; k < 256; k++) {
            ulonglong2 a = sS2[k * NQ2 + egp];
            u64 W = pk2(Wsv1[k * 64 + f]);
            fma2(acc[0], a.x, W); fma2(acc[1], a.y, W);
        }
        float r[4]; un4(acc, r);
        *(float4*)&sT1[f * ST + egp * 4] = make_float4(r[0], r[1], r[2], r[3]);
    }
    __syncthreads();

    // ---- Stage 4a: silu in place on rows 0..127 of sO0 ----
    {
        const int e = t & 15;
#pragma unroll
        for (int it = 0; it < 8; it++) {
            int j = (t >> 4) + 16 * it;
            float x = sO0[j * ST + e];
            sO0[j * ST + e] = x / (1.f + __expf(-x));
        }
    }
    // ---- Stage 4b: w = lat @ Wenv -> sS rows 0..191 ----
    {
        const int jj = t & 63, egp = t >> 6;
        u64 a0[2] = {0,0}, a1[2] = {0,0}, a2[2] = {0,0};
#pragma unroll 4
        for (int k = 0; k < 64; k++) {
            ulonglong2 a = sL2[k * NQ2 + egp];
            u64 W0 = pk2(Wenv[k * 192 + jj]);
            u64 W1 = pk2(Wenv[k * 192 + 64 + jj]);
            u64 W2 = pk2(Wenv[k * 192 + 128 + jj]);
            fma2(a0[0], a.x, W0); fma2(a0[1], a.y, W0);
            fma2(a1[0], a.x, W1); fma2(a1[1], a.y, W1);
            fma2(a2[0], a.x, W2); fma2(a2[1], a.y, W2);
        }
        __syncthreads();   // all reads of sS (stage 3) done before overwrite
        float r0[4], r1[4], r2[4];
        un4(a0, r0); un4(a1, r1); un4(a2, r2);
        *(float4*)&sS[jj * ST + egp * 4]         = make_float4(r0[0], r0[1], r0[2], r0[3]);
        *(float4*)&sS[(jj + 64) * ST + egp * 4]  = make_float4(r1[0], r1[1], r1[2], r1[3]);
        *(float4*)&sS[(jj + 128) * ST + egp * 4] = make_float4(r2[0], r2[1], r2[2], r2[3]);
    }
    // ---- Stage 4c: vector path (cross folded into epilogue) ----
    {
        const int f = t & 63, egp = t >> 6;
        u64 pAx[2]={0,0}, pAy[2]={0,0}, pAz[2]={0,0};
        u64 pBx[2]={0,0}, pBy[2]={0,0}, pBz[2]={0,0};
#pragma unroll 2
        for (int c = 0; c < 128; c++) {
            ulonglong2 vx = sV2[(c * 3 + 0) * NQ2 + egp];
            ulonglong2 vy = sV2[(c * 3 + 1) * NQ2 + egp];
            ulonglong2 vz = sV2[(c * 3 + 2) * NQ2 + egp];
            u64 W1 = pk2(Wvs1[c * 64 + f]);
            u64 W2 = pk2(Wvv1[c * 64 + f]);
            fma2(pAx[0], vx.x, W1); fma2(pAx[1], vx.y, W1);
            fma2(pAy[0], vy.x, W1); fma2(pAy[1], vy.y, W1);
            fma2(pAz[0], vz.x, W1); fma2(pAz[1], vz.y, W1);
            fma2(pBx[0], vx.x, W2); fma2(pBx[1], vx.y, W2);
            fma2(pBy[0], vy.x, W2); fma2(pBy[1], vy.y, W2);
            fma2(pBz[0], vz.x, W2); fma2(pBz[1], vz.y, W2);
        }
        float Ax[4], Ay[4], Az[4], Bx[4], By[4], Bz[4];
        un4(pAx, Ax); un4(pAy, Ay); un4(pAz, Az);
        un4(pBx, Bx); un4(pBy, By); un4(pBz, Bz);
        float4 s0 = *(const float4*)&sSh[0 * ST + egp * 4];
        float4 sx = *(const float4*)&sSh[1 * ST + egp * 4];
        float4 sy = *(const float4*)&sSh[2 * ST + egp * 4];
        float4 sz = *(const float4*)&sSh[3 * ST + egp * 4];
        float4 t1 = *(const float4*)&sT1[f * ST + egp * 4];
        float4 gg = *(const float4*)&sO0[(128 + f) * ST + egp * 4];
        float4 ox, oy, oz;
#pragma unroll
        for (int s = 0; s < 4; s++) {
            float g = 1.f / (1.f + __expf(-((const float*)&gg)[s]));
            float cx = (By[s] * ((const float*)&sz)[s] - Bz[s] * ((const float*)&sy)[s]) * INV_SQ2;
            float cy = (Bz[s] * ((const float*)&sx)[s] - Bx[s] * ((const float*)&sz)[s]) * INV_SQ2;
            float cz = (Bx[s] * ((const float*)&sy)[s] - By[s] * ((const float*)&sx)[s]) * INV_SQ2;
            float t1v = ((const float*)&t1)[s];
            float s0v = ((const float*)&s0)[s];
            ((float*)&ox)[s] = g * (s0v * Ax[s] + cx + t1v * ((const float*)&sx)[s]);
            ((float*)&oy)[s] = g * (s0v * Ay[s] + cy + t1v * ((const float*)&sy)[s]);
            ((float*)&oz)[s] = g * (s0v * Az[s] + cz + t1v * ((const float*)&sz)[s]);
        }
        *(float4*)&sOV[(f * 3 + 0) * ST + egp * 4] = ox;
        *(float4*)&sOV[(f * 3 + 1) * ST + egp * 4] = oy;
        *(float4*)&sOV[(f * 3 + 2) * ST + egp * 4] = oz;
    }
    __syncthreads();

    // ---- Stage 5a: s_out = (silu_s @ Wp_s) * w[:128], scatter ----
    {
        const int jj = t & 63, egp = t >> 6;
        u64 a0[2] = {0,0}, a1[2] = {0,0};
#pragma unroll 4
        for (int k = 0; k < 128; k++) {
            ulonglong2 a = sO02[k * NQ2 + egp];
            u64 WA = pk2(Wps[k * 128 + jj]);
            u64 WB = pk2(Wps[k * 128 + 64 + jj]);
            fma2(a0[0], a.x, WA); fma2(a0[1], a.y, WA);
            fma2(a1[0], a.x, WB); fma2(a1[1], a.y, WB);
        }
        float r0[4], r1[4];
        un4(a0, r0); un4(a1, r1);
        float4 w0 = *(const float4*)&sS[jj * ST + egp * 4];
        float4 w1 = *(const float4*)&sS[(jj + 64) * ST + egp * 4];
#pragma unroll
        for (int s = 0; s < 4; s++) {
            int c = sC[egp * 4 + s];
            atomicAdd(&out[c * 320 + jj],
                      r0[s] * ((const float*)&w0)[s] * 0.25f);
            atomicAdd(&out[c * 320 + 64 + jj],
                      r1[s] * ((const float*)&w1)[s] * 0.25f);
        }
    }
    // ---- Stage 5b: v_out = (v @ Wp_v) * w[128+f2], scatter ----
    {
        const int f2 = t & 63, egp = t >> 6;
        u64 pVx[2]={0,0}, pVy[2]={0,0}, pVz[2]={0,0};
#pragma unroll 2
        for (int kf = 0; kf < 64; kf++) {
            ulonglong2 vx = sOV2[(kf * 3 + 0) * NQ2 + egp];
            ulonglong2 vy = sOV2[(kf * 3 + 1) * NQ2 + egp];
            ulonglong2 vz = sOV2[(kf * 3 + 2) * NQ2 + egp];
            u64 W = pk2(Wpv[kf * 64 + f2]);
            fma2(pVx[0], vx.x, W); fma2(pVx[1], vx.y, W);
            fma2(pVy[0], vy.x, W); fma2(pVy[1], vy.y, W);
            fma2(pVz[0], vz.x, W); fma2(pVz[1], vz.y, W);
        }
        float Vx[4], Vy[4], Vz[4];
        un4(pVx, Vx); un4(pVy, Vy); un4(pVz, Vz);
        float4 wv = *(const float4*)&sS[(128 + f2) * ST + egp * 4];
#pragma unroll
        for (int s = 0; s < 4; s++) {
            int c = sC[egp * 4 + s];
            float ww = ((const float*)&wv)[s] * 0.25f;
            atomicAdd(&out[c * 320 + 128 + f2 * 3 + 0], Vx[s] * ww);
            atomicAdd(&out[c * 320 + 128 + f2 * 3 + 1], Vy[s] * ww);
            atomicAdd(&out[c * 320 + 128 + f2 * 3 + 2], Vz[s] * ww);
        }
    }
}

extern "C" void kernel_launch(void* const* d_in, const int* in_sizes, int n_in,
                              void* d_out, int out_size)
{
    const float* latents = (const float*)d_in[0];
    const float* nodef   = (const float*)d_in[1];
    const float* edgef   = (const float*)d_in[2];
    const float* esh     = (const float*)d_in[3];
    const int*   eidx    = (const int*)d_in[4];
    /* d_in[5] atom_type unused */
    const int*   act     = (const int*)d_in[6];
    const float* gsn  = (const float*)d_in[7];
    const float* bsn  = (const float*)d_in[8];
    const float* gvn  = (const float*)d_in[9];
    const float* gse  = (const float*)d_in[10];
    const float* bse  = (const float*)d_in[11];
    const float* gve  = (const float*)d_in[12];
    const float* Wss0 = (const float*)d_in[13];
    const float* Wvv0 = (const float*)d_in[14];
    const float* Wsv1 = (const float*)d_in[15];
    const float* Wvs1 = (const float*)d_in[16];
    const float* Wvv1 = (const float*)d_in[17];
    const float* Wps  = (const float*)d_in[18];
    const float* Wpv  = (const float*)d_in[19];
    const float* Wenv = (const float*)d_in[20];
    const float* Wrs  = (const float*)d_in[21];
    const float* Wrv  = (const float*)d_in[22];
    float* out = (float*)d_out;

    const size_t NODE_SMEM = (16384 + 4096 + 320 + 8) * sizeof(float);
    const size_t EDGE_SMEM = SMEM_EDGE_FLOATS * sizeof(float);

    cudaFuncSetAttribute(node_kernel, cudaFuncAttributeMaxDynamicSharedMemorySize,
                         (int)NODE_SMEM);
    cudaFuncSetAttribute(edge_kernel, cudaFuncAttributeMaxDynamicSharedMemorySize,
                         (int)EDGE_SMEM);

    node_kernel<<<296, 128, NODE_SMEM>>>(nodef, gsn, bsn, gvn, Wrs, Wrv, out);
    edge_kernel<<<10000, 256, EDGE_SMEM>>>(latents, edgef, esh, eidx, act,
                                           gse, bse, gve,
                                           Wss0, Wvv0, Wsv1, Wvs1, Wvv1,
                                           Wps, Wpv, Wenv, out);
}

// round 8
// speedup vs baseline: 2.2813x; 1.2082x over previous
#include <cuda_runtime.h>
#include <math.h>

#define N_NODES 10000
#define N_EDGES 160000
#define NSC 128
#define NVC 64
#define LATD 64
#define EPSLN 1e-5f
#define INV_SQ3 0.57735026918962576f
#define INV_SQ2 0.70710678118654752f

typedef unsigned long long u64;

// packed f32x2 helpers (FFMA2 path — only reachable via PTX)
__device__ __forceinline__ u64 pk2(float w) {
    u64 r; asm("mov.b64 %0, {%1, %1};" : "=l"(r) : "f"(w)); return r;
}
__device__ __forceinline__ void fma2(u64& acc, u64 a, u64 b) {
    asm("fma.rn.f32x2 %0, %1, %2, %0;" : "+l"(acc) : "l"(a), "l"(b));
}
__device__ __forceinline__ float2 up(u64 v) {
    union { u64 u; float2 f; } x; x.u = v; return x.f;
}
__device__ __forceinline__ void un4(const u64* p, float* f) {
    float2 a = up(p[0]), b = up(p[1]);
    f[0] = a.x; f[1] = a.y; f[2] = b.x; f[3] = b.y;
}

// scratch: LayerNormed node features
__device__ float g_ns[N_NODES * NSC];       // 5.12 MB
__device__ float g_nv[N_NODES * NVC * 3];   // 7.68 MB

// packed weight scratch (filled by prep_kernel each launch)
__device__ float4 w_ss0p[256 * 64];   // (Wss0[k][j], [64+j], [128+j], 0)
__device__ float4 w_vv0p[128 * 64];   // same for Wvv0
__device__ float4 w_envp[64 * 64];    // same for Wenv
__device__ float2 w_psp[128 * 64];    // (Wps[k][j], Wps[k][64+j])
__device__ float2 w_vsvv[128 * 64];   // (Wvs1[c][f], Wvv1[c][f])
__device__ float2 w_sv1p[128 * 64];   // (Wsv1[2k][f], Wsv1[2k+1][f])
__device__ float2 w_pvp[32 * 64];     // (Wpv[2k][f], Wpv[2k+1][f])

__global__ void prep_kernel(
    const float* __restrict__ Wss0, const float* __restrict__ Wvv0,
    const float* __restrict__ Wenv, const float* __restrict__ Wps,
    const float* __restrict__ Wvs1, const float* __restrict__ Wvv1,
    const float* __restrict__ Wsv1, const float* __restrict__ Wpv)
{
    int i = blockIdx.x * blockDim.x + threadIdx.x;   // 0 .. 256*64-1
    int k = i >> 6, j = i & 63;
    w_ss0p[i] = make_float4(Wss0[k * 192 + j], Wss0[k * 192 + 64 + j],
                            Wss0[k * 192 + 128 + j], 0.f);
    if (k < 128) {
        w_vv0p[i] = make_float4(Wvv0[k * 192 + j], Wvv0[k * 192 + 64 + j],
                                Wvv0[k * 192 + 128 + j], 0.f);
        w_psp[i]  = make_float2(Wps[k * 128 + j], Wps[k * 128 + 64 + j]);
        w_vsvv[i] = make_float2(Wvs1[k * 64 + j], Wvv1[k * 64 + j]);
        w_sv1p[i] = make_float2(Wsv1[(2 * k) * 64 + j], Wsv1[(2 * k + 1) * 64 + j]);
    }
    if (k < 64)
        w_envp[i] = make_float4(Wenv[k * 192 + j], Wenv[k * 192 + 64 + j],
                                Wenv[k * 192 + 128 + j], 0.f);
    if (k < 32)
        w_pvp[i] = make_float2(Wpv[(2 * k) * 64 + j], Wpv[(2 * k + 1) * 64 + j]);
}

__device__ __forceinline__ float brsum(float v, volatile float* red, int t) {
#pragma unroll
    for (int o = 16; o; o >>= 1) v += __shfl_xor_sync(0xffffffffu, v, o);
    __syncthreads();
    if ((t & 31) == 0) red[t >> 5] = v;
    __syncthreads();
    return red[0] + red[1] + red[2] + red[3];
}

// ---------------------------------------------------------------------------
// Node kernel: separable LN -> g_ns/g_nv, residual (Wr_s, Wr_v) -> out
// ---------------------------------------------------------------------------
__global__ void __launch_bounds__(128, 2) node_kernel(
    const float* __restrict__ nf,
    const float* __restrict__ gsn, const float* __restrict__ bsn,
    const float* __restrict__ gvn,
    const float* __restrict__ Wrs, const float* __restrict__ Wrv,
    float* __restrict__ out)
{
    extern __shared__ float sm[];
    float* wS  = sm;             // 128*128
    float* wV  = sm + 16384;     // 64*64
    float* sb  = sm + 20480;     // 320
    float* red = sm + 20800;     // 8
    const int t = threadIdx.x;

    for (int i = t; i < 16384; i += 128) wS[i] = Wrs[i];
    for (int i = t; i < 4096;  i += 128) wV[i] = Wrv[i];
    __syncthreads();

    for (int n = blockIdx.x; n < N_NODES; n += gridDim.x) {
        const float* row = nf + n * 320;
        sb[t] = row[t];
        sb[128 + t] = row[128 + t];
        if (t < 64) sb[256 + t] = row[256 + t];
        __syncthreads();

        float x = sb[t];
        float ssum = brsum(x, red, t);
        float ssq  = brsum(x * x, red, t);
        float mu = ssum * (1.f / 128.f);
        float var = ssq * (1.f / 128.f) - mu * mu;
        float rsg = rsqrtf(var + EPSLN);
        g_ns[n * NSC + t] = (x - mu) * rsg * gsn[t] + bsn[t];

        float v1 = sb[128 + t];
        float v2 = (t < 64) ? sb[256 + t] : 0.f;
        float vq = brsum(v1 * v1 + v2 * v2, red, t);
        float vsc = rsqrtf(vq * (1.f / 64.f) + EPSLN);
        g_nv[n * 192 + t] = v1 * vsc * gvn[t / 3];
        if (t < 64) g_nv[n * 192 + 128 + t] = v2 * vsc * gvn[(128 + t) / 3];

        float acc = 0.f;
#pragma unroll 8
        for (int k = 0; k < 128; k++) acc += sb[k] * wS[k * 128 + t];
        out[n * 320 + t] = acc;

        {
            int f = t & 63, d = t >> 6;
            float a = 0.f;
#pragma unroll 8
            for (int c = 0; c < 64; c++) a += sb[128 + c * 3 + d] * wV[c * 64 + f];
            out[n * 320 + 128 + f * 3 + d] = a;
        }
        if (t < 64) {
            float a = 0.f;
#pragma unroll 8
            for (int c = 0; c < 64; c++) a += sb[128 + c * 3 + 2] * wV[c * 64 + t];
            out[n * 320 + 128 + t * 3 + 2] = a;
        }
        __syncthreads();
    }
}

// ---------------------------------------------------------------------------
// Edge kernel: 16 edges/block, 256 threads, 2 CTAs/SM, packed-f32x2 GEMMs,
// packed vector weight loads from __device__ scratch
// ---------------------------------------------------------------------------
#define ST 20
#define NQ2 5                  // ulonglong2 (16B) per row
#define OFF_S    0             // [256][20]
#define OFF_V    5120          // [384][20]
#define OFF_DOT  12800         // [128][20]
#define OFF_O0   15360         // [192][20]
#define OFF_OV   19200         // [192][20]
#define OFF_T1   23040         // [64][20]
#define OFF_LAT  24320         // [64][20]
#define OFF_SH   25600         // [4][20]
#define OFF_GSE  25680
#define OFF_BSE  25808
#define OFF_GVE  25936
#define OFF_C    26000         // 16 ints
#define SMEM_EDGE_FLOATS 26016

__global__ void __launch_bounds__(256, 2) edge_kernel(
    const float* __restrict__ latents, const float* __restrict__ ef,
    const float* __restrict__ esh, const int* __restrict__ eidx,
    const int* __restrict__ act,
    const float* __restrict__ gse, const float* __restrict__ bse,
    const float* __restrict__ gve,
    float* __restrict__ out)
{
    extern __shared__ float sm[];
    float* sS   = sm + OFF_S;
    float* sV   = sm + OFF_V;
    float* sDot = sm + OFF_DOT;
    float* sO0  = sm + OFF_O0;
    float* sOV  = sm + OFF_OV;
    float* sT1  = sm + OFF_T1;
    float* sLat = sm + OFF_LAT;
    float* sSh  = sm + OFF_SH;
    float* pGse = sm + OFF_GSE;
    float* pBse = sm + OFF_BSE;
    float* pGve = sm + OFF_GVE;
    int*   sC   = (int*)(sm + OFF_C);

    const int t = threadIdx.x;

    if (t < 128) { pGse[t] = gse[t]; pBse[t] = bse[t]; }
    else if (t < 192) { pGve[t - 128] = gve[t - 128]; }
    __syncthreads();

    // ---- Stage 1: load + edge LN (16 lanes/edge), float4 global loads ----
    {
        const int e = ((t >> 5) * 2) + ((t & 31) >> 4), l = t & 15;
        const int eg = blockIdx.x * 16 + e;
        const int ae = act[eg];
        const int c  = eidx[ae];
        if (l == 0) {
            sC[e] = c;
            sSh[0 * ST + e] = esh[eg * 4 + 0];
            sSh[1 * ST + e] = esh[eg * 4 + 1];
            sSh[2 * ST + e] = esh[eg * 4 + 2];
            sSh[3 * ST + e] = esh[eg * 4 + 3];
        }
        {
            const float4* lq = (const float4*)(latents + (size_t)ae * 64);
            float4 v = lq[l];
            sLat[(4 * l + 0) * ST + e] = v.x;
            sLat[(4 * l + 1) * ST + e] = v.y;
            sLat[(4 * l + 2) * ST + e] = v.z;
            sLat[(4 * l + 3) * ST + e] = v.w;
        }
        {
            const float4* nq = (const float4*)(g_ns + (size_t)c * 128);
            float4 a = nq[l], b = nq[l + 16];
#pragma unroll
            for (int s = 0; s < 4; s++) {
                sS[(4 * l + s) * ST + e]      = ((const float*)&a)[s];
                sS[(64 + 4 * l + s) * ST + e] = ((const float*)&b)[s];
            }
        }
        {
            const float4* nq = (const float4*)(g_nv + (size_t)c * 192);
            float4 a = nq[l], b = nq[l + 16], cc4 = nq[l + 32];
#pragma unroll
            for (int s = 0; s < 4; s++) {
                sV[(4 * l + s) * ST + e]       = ((const float*)&a)[s];
                sV[(64 + 4 * l + s) * ST + e]  = ((const float*)&b)[s];
                sV[(128 + 4 * l + s) * ST + e] = ((const float*)&cc4)[s];
            }
        }
        const float4* eq = (const float4*)(ef + (size_t)eg * 320);
        float4 ra = eq[l], rb = eq[l + 16];
        float sum = ra.x + ra.y + ra.z + ra.w + rb.x + rb.y + rb.z + rb.w;
        float ssq = ra.x*ra.x + ra.y*ra.y + ra.z*ra.z + ra.w*ra.w
                  + rb.x*rb.x + rb.y*rb.y + rb.z*rb.z + rb.w*rb.w;
#pragma unroll
        for (int o = 1; o < 16; o <<= 1) {
            sum += __shfl_xor_sync(0xffffffffu, sum, o);
            ssq += __shfl_xor_sync(0xffffffffu, ssq, o);
        }
        float mu  = sum * (1.f / 128.f);
        float var = ssq * (1.f / 128.f) - mu * mu;
        float rsg = rsqrtf(var + EPSLN);
#pragma unroll
        for (int s = 0; s < 4; s++) {
            int j0 = 4 * l + s, j1 = 64 + 4 * l + s;
            sS[(128 + j0) * ST + e] = (((const float*)&ra)[s] - mu) * rsg * pGse[j0] + pBse[j0];
            sS[(128 + j1) * ST + e] = (((const float*)&rb)[s] - mu) * rsg * pGse[j1] + pBse[j1];
        }
        float4 va = eq[32 + l], vb = eq[48 + l], vc = eq[64 + l];
        float sv2 = va.x*va.x + va.y*va.y + va.z*va.z + va.w*va.w
                  + vb.x*vb.x + vb.y*vb.y + vb.z*vb.z + vb.w*vb.w
                  + vc.x*vc.x + vc.y*vc.y + vc.z*vc.z + vc.w*vc.w;
#pragma unroll
        for (int o = 1; o < 16; o <<= 1)
            sv2 += __shfl_xor_sync(0xffffffffu, sv2, o);
        float vsc = rsqrtf(sv2 * (1.f / 64.f) + EPSLN);
#pragma unroll
        for (int s = 0; s < 4; s++) {
            int i0 = 4 * l + s, i1 = 64 + 4 * l + s, i2 = 128 + 4 * l + s;
            sV[(192 + i0) * ST + e] = ((const float*)&va)[s] * vsc * pGve[i0 / 3];
            sV[(192 + i1) * ST + e] = ((const float*)&vb)[s] * vsc * pGve[i1 / 3];
            sV[(192 + i2) * ST + e] = ((const float*)&vc)[s] * vsc * pGve[i2 / 3];
        }
    }
    __syncthreads();

    // ---- dotV = (V . sh1)/sqrt3 ----
    {
        const int e = t & 15;
        float shx = sSh[1 * ST + e], shy = sSh[2 * ST + e], shz = sSh[3 * ST + e];
#pragma unroll
        for (int it = 0; it < 8; it++) {
            int cc = (t >> 4) + 16 * it;
            sDot[cc * ST + e] =
                (sV[(cc * 3 + 0) * ST + e] * shx +
                 sV[(cc * 3 + 1) * ST + e] * shy +
                 sV[(cc * 3 + 2) * ST + e] * shz) * INV_SQ3;
        }
    }
    __syncthreads();

    const ulonglong2* sS2  = (const ulonglong2*)sS;
    const ulonglong2* sD2  = (const ulonglong2*)sDot;
    const ulonglong2* sL2  = (const ulonglong2*)sLat;
    const ulonglong2* sV2  = (const ulonglong2*)sV;
    const ulonglong2* sO02 = (const ulonglong2*)sO0;
    const ulonglong2* sOV2 = (const ulonglong2*)sOV;

    // ---- Stage 2: out0 = sh0*(S@Wss0) + dot@Wvv0 ----
    {
        const int jj = t & 63, egp = t >> 6;
        u64 aS[3][2] = {{0,0},{0,0},{0,0}};
        u64 aD[3][2] = {{0,0},{0,0},{0,0}};
#pragma unroll 4
        for (int k = 0; k < 256; k++) {
            ulonglong2 a = sS2[k * NQ2 + egp];
            float4 w = w_ss0p[k * 64 + jj];
            u64 W0 = pk2(w.x), W1 = pk2(w.y), W2 = pk2(w.z);
            fma2(aS[0][0], a.x, W0); fma2(aS[0][1], a.y, W0);
            fma2(aS[1][0], a.x, W1); fma2(aS[1][1], a.y, W1);
            fma2(aS[2][0], a.x, W2); fma2(aS[2][1], a.y, W2);
        }
#pragma unroll 4
        for (int k = 0; k < 128; k++) {
            ulonglong2 a = sD2[k * NQ2 + egp];
            float4 w = w_vv0p[k * 64 + jj];
            u64 W0 = pk2(w.x), W1 = pk2(w.y), W2 = pk2(w.z);
            fma2(aD[0][0], a.x, W0); fma2(aD[0][1], a.y, W0);
            fma2(aD[1][0], a.x, W1); fma2(aD[1][1], a.y, W1);
            fma2(aD[2][0], a.x, W2); fma2(aD[2][1], a.y, W2);
        }
        float4 s0 = *(const float4*)&sSh[0 * ST + egp * 4];
        float S0[4], S1[4], S2[4], D0[4], D1[4], D2[4];
        un4(aS[0], S0); un4(aS[1], S1); un4(aS[2], S2);
        un4(aD[0], D0); un4(aD[1], D1); un4(aD[2], D2);
        float4 o0, o1, o2;
#pragma unroll
        for (int s = 0; s < 4; s++) {
            float sv = ((const float*)&s0)[s];
            ((float*)&o0)[s] = sv * S0[s] + D0[s];
            ((float*)&o1)[s] = sv * S1[s] + D1[s];
            ((float*)&o2)[s] = sv * S2[s] + D2[s];
        }
        *(float4*)&sO0[jj * ST + egp * 4]         = o0;
        *(float4*)&sO0[(jj + 64) * ST + egp * 4]  = o1;
        *(float4*)&sO0[(jj + 128) * ST + egp * 4] = o2;
    }
    __syncthreads();

    // ---- Stage 3: t1 = S @ Wsv1 (paired k) ----
    {
        const int f = t & 63, egp = t >> 6;
        u64 acc[2] = {0, 0};
#pragma unroll 4
        for (int kk = 0; kk < 128; kk++) {
            ulonglong2 a0 = sS2[(2 * kk) * NQ2 + egp];
            ulonglong2 a1 = sS2[(2 * kk + 1) * NQ2 + egp];
            float2 w = w_sv1p[kk * 64 + f];
            u64 W0 = pk2(w.x), W1 = pk2(w.y);
            fma2(acc[0], a0.x, W0); fma2(acc[1], a0.y, W0);
            fma2(acc[0], a1.x, W1); fma2(acc[1], a1.y, W1);
        }
        float r[4]; un4(acc, r);
        *(float4*)&sT1[f * ST + egp * 4] = make_float4(r[0], r[1], r[2], r[3]);
    }
    __syncthreads();

    // ---- Stage 4a: silu in place on rows 0..127 of sO0 ----
    {
        const int e = t & 15;
#pragma unroll
        for (int it = 0; it < 8; it++) {
            int j = (t >> 4) + 16 * it;
            float x = sO0[j * ST + e];
            sO0[j * ST + e] = x / (1.f + __expf(-x));
        }
    }
    // ---- Stage 4b: w = lat @ Wenv -> sS rows 0..191 ----
    {
        const int jj = t & 63, egp = t >> 6;
        u64 a0[2] = {0,0}, a1[2] = {0,0}, a2[2] = {0,0};
#pragma unroll 4
        for (int k = 0; k < 64; k++) {
            ulonglong2 a = sL2[k * NQ2 + egp];
            float4 w = w_envp[k * 64 + jj];
            u64 W0 = pk2(w.x), W1 = pk2(w.y), W2 = pk2(w.z);
            fma2(a0[0], a.x, W0); fma2(a0[1], a.y, W0);
            fma2(a1[0], a.x, W1); fma2(a1[1], a.y, W1);
            fma2(a2[0], a.x, W2); fma2(a2[1], a.y, W2);
        }
        __syncthreads();   // all reads of sS (stage 3) done before overwrite
        float r0[4], r1[4], r2[4];
        un4(a0, r0); un4(a1, r1); un4(a2, r2);
        *(float4*)&sS[jj * ST + egp * 4]         = make_float4(r0[0], r0[1], r0[2], r0[3]);
        *(float4*)&sS[(jj + 64) * ST + egp * 4]  = make_float4(r1[0], r1[1], r1[2], r1[3]);
        *(float4*)&sS[(jj + 128) * ST + egp * 4] = make_float4(r2[0], r2[1], r2[2], r2[3]);
    }
    // ---- Stage 4c: vector path (cross folded into epilogue) ----
    {
        const int f = t & 63, egp = t >> 6;
        u64 pAx[2]={0,0}, pAy[2]={0,0}, pAz[2]={0,0};
        u64 pBx[2]={0,0}, pBy[2]={0,0}, pBz[2]={0,0};
#pragma unroll 2
        for (int c = 0; c < 128; c++) {
            ulonglong2 vx = sV2[(c * 3 + 0) * NQ2 + egp];
            ulonglong2 vy = sV2[(c * 3 + 1) * NQ2 + egp];
            ulonglong2 vz = sV2[(c * 3 + 2) * NQ2 + egp];
            float2 w = w_vsvv[c * 64 + f];
            u64 W1 = pk2(w.x), W2 = pk2(w.y);
            fma2(pAx[0], vx.x, W1); fma2(pAx[1], vx.y, W1);
            fma2(pAy[0], vy.x, W1); fma2(pAy[1], vy.y, W1);
            fma2(pAz[0], vz.x, W1); fma2(pAz[1], vz.y, W1);
            fma2(pBx[0], vx.x, W2); fma2(pBx[1], vx.y, W2);
            fma2(pBy[0], vy.x, W2); fma2(pBy[1], vy.y, W2);
            fma2(pBz[0], vz.x, W2); fma2(pBz[1], vz.y, W2);
        }
        float Ax[4], Ay[4], Az[4], Bx[4], By[4], Bz[4];
        un4(pAx, Ax); un4(pAy, Ay); un4(pAz, Az);
        un4(pBx, Bx); un4(pBy, By); un4(pBz, Bz);
        float4 s0 = *(const float4*)&sSh[0 * ST + egp * 4];
        float4 sx = *(const float4*)&sSh[1 * ST + egp * 4];
        float4 sy = *(const float4*)&sSh[2 * ST + egp * 4];
        float4 sz = *(const float4*)&sSh[3 * ST + egp * 4];
        float4 t1 = *(const float4*)&sT1[f * ST + egp * 4];
        float4 gg = *(const float4*)&sO0[(128 + f) * ST + egp * 4];
        float4 ox, oy, oz;
#pragma unroll
        for (int s = 0; s < 4; s++) {
            float g = 1.f / (1.f + __expf(-((const float*)&gg)[s]));
            float cx = (By[s] * ((const float*)&sz)[s] - Bz[s] * ((const float*)&sy)[s]) * INV_SQ2;
            float cy = (Bz[s] * ((const float*)&sx)[s] - Bx[s] * ((const float*)&sz)[s]) * INV_SQ2;
            float cz = (Bx[s] * ((const float*)&sy)[s] - By[s] * ((const float*)&sx)[s]) * INV_SQ2;
            float t1v = ((const float*)&t1)[s];
            float s0v = ((const float*)&s0)[s];
            ((float*)&ox)[s] = g * (s0v * Ax[s] + cx + t1v * ((const float*)&sx)[s]);
            ((float*)&oy)[s] = g * (s0v * Ay[s] + cy + t1v * ((const float*)&sy)[s]);
            ((float*)&oz)[s] = g * (s0v * Az[s] + cz + t1v * ((const float*)&sz)[s]);
        }
        *(float4*)&sOV[(f * 3 + 0) * ST + egp * 4] = ox;
        *(float4*)&sOV[(f * 3 + 1) * ST + egp * 4] = oy;
        *(float4*)&sOV[(f * 3 + 2) * ST + egp * 4] = oz;
    }
    __syncthreads();

    // ---- Stage 5a: s_out = (silu_s @ Wp_s) * w[:128], scatter ----
    {
        const int jj = t & 63, egp = t >> 6;
        u64 a0[2] = {0,0}, a1[2] = {0,0};
#pragma unroll 4
        for (int k = 0; k < 128; k++) {
            ulonglong2 a = sO02[k * NQ2 + egp];
            float2 w = w_psp[k * 64 + jj];
            u64 WA = pk2(w.x), WB = pk2(w.y);
            fma2(a0[0], a.x, WA); fma2(a0[1], a.y, WA);
            fma2(a1[0], a.x, WB); fma2(a1[1], a.y, WB);
        }
        float r0[4], r1[4];
        un4(a0, r0); un4(a1, r1);
        float4 w0 = *(const float4*)&sS[jj * ST + egp * 4];
        float4 w1 = *(const float4*)&sS[(jj + 64) * ST + egp * 4];
#pragma unroll
        for (int s = 0; s < 4; s++) {
            int c = sC[egp * 4 + s];
            atomicAdd(&out[c * 320 + jj],
                      r0[s] * ((const float*)&w0)[s] * 0.25f);
            atomicAdd(&out[c * 320 + 64 + jj],
                      r1[s] * ((const float*)&w1)[s] * 0.25f);
        }
    }
    // ---- Stage 5b: v_out = (v @ Wp_v) * w[128+f2], scatter (paired kf) ----
    {
        const int f2 = t & 63, egp = t >> 6;
        u64 pVx[2]={0,0}, pVy[2]={0,0}, pVz[2]={0,0};
#pragma unroll 2
        for (int kk = 0; kk < 32; kk++) {
            float2 w = w_pvp[kk * 64 + f2];
            u64 W0 = pk2(w.x), W1 = pk2(w.y);
            int kf0 = 2 * kk, kf1 = 2 * kk + 1;
            ulonglong2 vx0 = sOV2[(kf0 * 3 + 0) * NQ2 + egp];
            ulonglong2 vy0 = sOV2[(kf0 * 3 + 1) * NQ2 + egp];
            ulonglong2 vz0 = sOV2[(kf0 * 3 + 2) * NQ2 + egp];
            fma2(pVx[0], vx0.x, W0); fma2(pVx[1], vx0.y, W0);
            fma2(pVy[0], vy0.x, W0); fma2(pVy[1], vy0.y, W0);
            fma2(pVz[0], vz0.x, W0); fma2(pVz[1], vz0.y, W0);
            ulonglong2 vx1 = sOV2[(kf1 * 3 + 0) * NQ2 + egp];
            ulonglong2 vy1 = sOV2[(kf1 * 3 + 1) * NQ2 + egp];
            ulonglong2 vz1 = sOV2[(kf1 * 3 + 2) * NQ2 + egp];
            fma2(pVx[0], vx1.x, W1); fma2(pVx[1], vx1.y, W1);
            fma2(pVy[0], vy1.x, W1); fma2(pVy[1], vy1.y, W1);
            fma2(pVz[0], vz1.x, W1); fma2(pVz[1], vz1.y, W1);
        }
        float Vx[4], Vy[4], Vz[4];
        un4(pVx, Vx); un4(pVy, Vy); un4(pVz, Vz);
        float4 wv = *(const float4*)&sS[(128 + f2) * ST + egp * 4];
#pragma unroll
        for (int s = 0; s < 4; s++) {
            int c = sC[egp * 4 + s];
            float ww = ((const float*)&wv)[s] * 0.25f;
            atomicAdd(&out[c * 320 + 128 + f2 * 3 + 0], Vx[s] * ww);
            atomicAdd(&out[c * 320 + 128 + f2 * 3 + 1], Vy[s] * ww);
            atomicAdd(&out[c * 320 + 128 + f2 * 3 + 2], Vz[s] * ww);
        }
    }
}

extern "C" void kernel_launch(void* const* d_in, const int* in_sizes, int n_in,
                              void* d_out, int out_size)
{
    const float* latents = (const float*)d_in[0];
    const float* nodef   = (const float*)d_in[1];
    const float* edgef   = (const float*)d_in[2];
    const float* esh     = (const float*)d_in[3];
    const int*   eidx    = (const int*)d_in[4];
    /* d_in[5] atom_type unused */
    const int*   act     = (const int*)d_in[6];
    const float* gsn  = (const float*)d_in[7];
    const float* bsn  = (const float*)d_in[8];
    const float* gvn  = (const float*)d_in[9];
    const float* gse  = (const float*)d_in[10];
    const float* bse  = (const float*)d_in[11];
    const float* gve  = (const float*)d_in[12];
    const float* Wss0 = (const float*)d_in[13];
    const float* Wvv0 = (const float*)d_in[14];
    const float* Wsv1 = (const float*)d_in[15];
    const float* Wvs1 = (const float*)d_in[16];
    const float* Wvv1 = (const float*)d_in[17];
    const float* Wps  = (const float*)d_in[18];
    const float* Wpv  = (const float*)d_in[19];
    const float* Wenv = (const float*)d_in[20];
    const float* Wrs  = (const float*)d_in[21];
    const float* Wrv  = (const float*)d_in[22];
    float* out = (float*)d_out;

    const size_t NODE_SMEM = (16384 + 4096 + 320 + 8) * sizeof(float);
    const size_t EDGE_SMEM = SMEM_EDGE_FLOATS * sizeof(float);

    cudaFuncSetAttribute(node_kernel, cudaFuncAttributeMaxDynamicSharedMemorySize,
                         (int)NODE_SMEM);
    cudaFuncSetAttribute(edge_kernel, cudaFuncAttributeMaxDynamicSharedMemorySize,
                         (int)EDGE_SMEM);

    prep_kernel<<<64, 256>>>(Wss0, Wvv0, Wenv, Wps, Wvs1, Wvv1, Wsv1, Wpv);
    node_kernel<<<296, 128, NODE_SMEM>>>(nodef, gsn, bsn, gvn, Wrs, Wrv, out);
    edge_kernel<<<10000, 256, EDGE_SMEM>>>(latents, edgef, esh, eidx, act,
                                           gse, bse, gve, out);
}

// round 9
// speedup vs baseline: 2.7049x; 1.1857x over previous
#include <cuda_runtime.h>
#include <math.h>

#define N_NODES 10000
#define N_EDGES 160000
#define NSC 128
#define NVC 64
#define LATD 64
#define EPSLN 1e-5f
#define INV_SQ3 0.57735026918962576f
#define INV_SQ2 0.70710678118654752f

typedef unsigned long long u64;

// packed f32x2 helpers (FFMA2 path — only reachable via PTX)
__device__ __forceinline__ u64 pk2(float w) {
    u64 r; asm("mov.b64 %0, {%1, %1};" : "=l"(r) : "f"(w)); return r;
}
__device__ __forceinline__ void fma2(u64& acc, u64 a, u64 b) {
    asm("fma.rn.f32x2 %0, %1, %2, %0;" : "+l"(acc) : "l"(a), "l"(b));
}
__device__ __forceinline__ void mul2(u64& a, u64 b) {
    asm("mul.rn.f32x2 %0, %0, %1;" : "+l"(a) : "l"(b));
}
__device__ __forceinline__ float2 up(u64 v) {
    union { u64 u; float2 f; } x; x.u = v; return x.f;
}
__device__ __forceinline__ void un4(const u64* p, float* f) {
    float2 a = up(p[0]), b = up(p[1]);
    f[0] = a.x; f[1] = a.y; f[2] = b.x; f[3] = b.y;
}

// scratch: LayerNormed node features
__device__ float g_ns[N_NODES * NSC];       // 5.12 MB
__device__ float g_nv[N_NODES * NVC * 3];   // 7.68 MB

// packed weight scratch (filled by prep_kernel each launch)
__device__ float4 w_ss0p[256 * 64];   // (Wss0[k][j], [64+j], [128+j], 0)
__device__ float4 w_vv0p[128 * 64];   // same for Wvv0
__device__ float4 w_envp[64 * 64];    // same for Wenv
__device__ float4 w_sv1q[64 * 64];    // (Wsv1[4k..4k+3][f])
__device__ float4 w_psq[64 * 64];     // (Wps[2k][j], Wps[2k][64+j], Wps[2k+1][j], Wps[2k+1][64+j])
__device__ float4 w_vsvvq[64 * 64];   // (Wvs1[2c][f], Wvv1[2c][f], Wvs1[2c+1][f], Wvv1[2c+1][f])
__device__ float4 w_pvq[16 * 64];     // (Wpv[4k..4k+3][f])

__global__ void prep_kernel(
    const float* __restrict__ Wss0, const float* __restrict__ Wvv0,
    const float* __restrict__ Wenv, const float* __restrict__ Wps,
    const float* __restrict__ Wvs1, const float* __restrict__ Wvv1,
    const float* __restrict__ Wsv1, const float* __restrict__ Wpv)
{
    int i = blockIdx.x * blockDim.x + threadIdx.x;   // 0 .. 256*64-1
    int k = i >> 6, j = i & 63;
    w_ss0p[i] = make_float4(Wss0[k * 192 + j], Wss0[k * 192 + 64 + j],
                            Wss0[k * 192 + 128 + j], 0.f);
    if (k < 128) {
        w_vv0p[i] = make_float4(Wvv0[k * 192 + j], Wvv0[k * 192 + 64 + j],
                                Wvv0[k * 192 + 128 + j], 0.f);
    }
    if (k < 64) {
        w_envp[i] = make_float4(Wenv[k * 192 + j], Wenv[k * 192 + 64 + j],
                                Wenv[k * 192 + 128 + j], 0.f);
        w_sv1q[i] = make_float4(Wsv1[(4 * k) * 64 + j], Wsv1[(4 * k + 1) * 64 + j],
                                Wsv1[(4 * k + 2) * 64 + j], Wsv1[(4 * k + 3) * 64 + j]);
        w_psq[i]  = make_float4(Wps[(2 * k) * 128 + j], Wps[(2 * k) * 128 + 64 + j],
                                Wps[(2 * k + 1) * 128 + j], Wps[(2 * k + 1) * 128 + 64 + j]);
        w_vsvvq[i] = make_float4(Wvs1[(2 * k) * 64 + j], Wvv1[(2 * k) * 64 + j],
                                 Wvs1[(2 * k + 1) * 64 + j], Wvv1[(2 * k + 1) * 64 + j]);
    }
    if (k < 16)
        w_pvq[i] = make_float4(Wpv[(4 * k) * 64 + j], Wpv[(4 * k + 1) * 64 + j],
                               Wpv[(4 * k + 2) * 64 + j], Wpv[(4 * k + 3) * 64 + j]);
}

__device__ __forceinline__ float brsum(float v, volatile float* red, int t) {
#pragma unroll
    for (int o = 16; o; o >>= 1) v += __shfl_xor_sync(0xffffffffu, v, o);
    __syncthreads();
    if ((t & 31) == 0) red[t >> 5] = v;
    __syncthreads();
    return red[0] + red[1] + red[2] + red[3];
}

// ---------------------------------------------------------------------------
// Node kernel: separable LN -> g_ns/g_nv, residual (Wr_s, Wr_v) -> out
// ---------------------------------------------------------------------------
__global__ void __launch_bounds__(128, 2) node_kernel(
    const float* __restrict__ nf,
    const float* __restrict__ gsn, const float* __restrict__ bsn,
    const float* __restrict__ gvn,
    const float* __restrict__ Wrs, const float* __restrict__ Wrv,
    float* __restrict__ out)
{
    extern __shared__ float sm[];
    float* wS  = sm;             // 128*128
    float* wV  = sm + 16384;     // 64*64
    float* sb  = sm + 20480;     // 320
    float* red = sm + 20800;     // 8
    const int t = threadIdx.x;

    for (int i = t; i < 16384; i += 128) wS[i] = Wrs[i];
    for (int i = t; i < 4096;  i += 128) wV[i] = Wrv[i];
    __syncthreads();

    for (int n = blockIdx.x; n < N_NODES; n += gridDim.x) {
        const float* row = nf + n * 320;
        sb[t] = row[t];
        sb[128 + t] = row[128 + t];
        if (t < 64) sb[256 + t] = row[256 + t];
        __syncthreads();

        float x = sb[t];
        float ssum = brsum(x, red, t);
        float ssq  = brsum(x * x, red, t);
        float mu = ssum * (1.f / 128.f);
        float var = ssq * (1.f / 128.f) - mu * mu;
        float rsg = rsqrtf(var + EPSLN);
        g_ns[n * NSC + t] = (x - mu) * rsg * gsn[t] + bsn[t];

        float v1 = sb[128 + t];
        float v2 = (t < 64) ? sb[256 + t] : 0.f;
        float vq = brsum(v1 * v1 + v2 * v2, red, t);
        float vsc = rsqrtf(vq * (1.f / 64.f) + EPSLN);
        g_nv[n * 192 + t] = v1 * vsc * gvn[t / 3];
        if (t < 64) g_nv[n * 192 + 128 + t] = v2 * vsc * gvn[(128 + t) / 3];

        float acc = 0.f;
#pragma unroll 8
        for (int k = 0; k < 128; k++) acc += sb[k] * wS[k * 128 + t];
        out[n * 320 + t] = acc;

        {
            int f = t & 63, d = t >> 6;
            float a = 0.f;
#pragma unroll 8
            for (int c = 0; c < 64; c++) a += sb[128 + c * 3 + d] * wV[c * 64 + f];
            out[n * 320 + 128 + f * 3 + d] = a;
        }
        if (t < 64) {
            float a = 0.f;
#pragma unroll 8
            for (int c = 0; c < 64; c++) a += sb[128 + c * 3 + 2] * wV[c * 64 + t];
            out[n * 320 + 128 + t * 3 + 2] = a;
        }
        __syncthreads();
    }
}

// ---------------------------------------------------------------------------
// Edge kernel: 16 edges/block, 256 threads, 2 CTAs/SM, packed-f32x2 GEMMs,
// k-split stage 2 with smem atomic reduction, quad-packed weight loads
// ---------------------------------------------------------------------------
#define ST 20
#define NQ2 5                  // ulonglong2 (16B) per row
#define OFF_S    0             // [256][20]
#define OFF_V    5120          // [384][20]
#define OFF_DOT  12800         // [128][20]
#define OFF_O0   15360         // [192][20]
#define OFF_OV   19200         // [192][20]
#define OFF_T1   23040         // [64][20]
#define OFF_LAT  24320         // [64][20]
#define OFF_SH   25600         // [4][20]
#define OFF_GSE  25680
#define OFF_BSE  25808
#define OFF_GVE  25936
#define OFF_C    26000         // 16 ints
#define SMEM_EDGE_FLOATS 26016

__global__ void __launch_bounds__(256, 2) edge_kernel(
    const float* __restrict__ latents, const float* __restrict__ ef,
    const float* __restrict__ esh, const int* __restrict__ eidx,
    const int* __restrict__ act,
    const float* __restrict__ gse, const float* __restrict__ bse,
    const float* __restrict__ gve,
    float* __restrict__ out)
{
    extern __shared__ float sm[];
    float* sS   = sm + OFF_S;
    float* sV   = sm + OFF_V;
    float* sDot = sm + OFF_DOT;
    float* sO0  = sm + OFF_O0;
    float* sOV  = sm + OFF_OV;
    float* sT1  = sm + OFF_T1;
    float* sLat = sm + OFF_LAT;
    float* sSh  = sm + OFF_SH;
    float* pGse = sm + OFF_GSE;
    float* pBse = sm + OFF_BSE;
    float* pGve = sm + OFF_GVE;
    int*   sC   = (int*)(sm + OFF_C);

    const int t = threadIdx.x;

    if (t < 128) { pGse[t] = gse[t]; pBse[t] = bse[t]; }
    else if (t < 192) { pGve[t - 128] = gve[t - 128]; }
    __syncthreads();

    // ---- Stage 1: load + edge LN (16 lanes/edge), float4 global loads ----
    {
        const int e = ((t >> 5) * 2) + ((t & 31) >> 4), l = t & 15;
        const int eg = blockIdx.x * 16 + e;
        const int ae = act[eg];
        const int c  = eidx[ae];
        if (l == 0) {
            sC[e] = c;
            sSh[0 * ST + e] = esh[eg * 4 + 0];
            sSh[1 * ST + e] = esh[eg * 4 + 1];
            sSh[2 * ST + e] = esh[eg * 4 + 2];
            sSh[3 * ST + e] = esh[eg * 4 + 3];
        }
        {
            const float4* lq = (const float4*)(latents + (size_t)ae * 64);
            float4 v = lq[l];
            sLat[(4 * l + 0) * ST + e] = v.x;
            sLat[(4 * l + 1) * ST + e] = v.y;
            sLat[(4 * l + 2) * ST + e] = v.z;
            sLat[(4 * l + 3) * ST + e] = v.w;
        }
        {
            const float4* nq = (const float4*)(g_ns + (size_t)c * 128);
            float4 a = nq[l], b = nq[l + 16];
#pragma unroll
            for (int s = 0; s < 4; s++) {
                sS[(4 * l + s) * ST + e]      = ((const float*)&a)[s];
                sS[(64 + 4 * l + s) * ST + e] = ((const float*)&b)[s];
            }
        }
        {
            const float4* nq = (const float4*)(g_nv + (size_t)c * 192);
            float4 a = nq[l], b = nq[l + 16], cc4 = nq[l + 32];
#pragma unroll
            for (int s = 0; s < 4; s++) {
                sV[(4 * l + s) * ST + e]       = ((const float*)&a)[s];
                sV[(64 + 4 * l + s) * ST + e]  = ((const float*)&b)[s];
                sV[(128 + 4 * l + s) * ST + e] = ((const float*)&cc4)[s];
            }
        }
        const float4* eq = (const float4*)(ef + (size_t)eg * 320);
        float4 ra = eq[l], rb = eq[l + 16];
        float sum = ra.x + ra.y + ra.z + ra.w + rb.x + rb.y + rb.z + rb.w;
        float ssq = ra.x*ra.x + ra.y*ra.y + ra.z*ra.z + ra.w*ra.w
                  + rb.x*rb.x + rb.y*rb.y + rb.z*rb.z + rb.w*rb.w;
#pragma unroll
        for (int o = 1; o < 16; o <<= 1) {
            sum += __shfl_xor_sync(0xffffffffu, sum, o);
            ssq += __shfl_xor_sync(0xffffffffu, ssq, o);
        }
        float mu  = sum * (1.f / 128.f);
        float var = ssq * (1.f / 128.f) - mu * mu;
        float rsg = rsqrtf(var + EPSLN);
#pragma unroll
        for (int s = 0; s < 4; s++) {
            int j0 = 4 * l + s, j1 = 64 + 4 * l + s;
            sS[(128 + j0) * ST + e] = (((const float*)&ra)[s] - mu) * rsg * pGse[j0] + pBse[j0];
            sS[(128 + j1) * ST + e] = (((const float*)&rb)[s] - mu) * rsg * pGse[j1] + pBse[j1];
        }
        float4 va = eq[32 + l], vb = eq[48 + l], vc = eq[64 + l];
        float sv2 = va.x*va.x + va.y*va.y + va.z*va.z + va.w*va.w
                  + vb.x*vb.x + vb.y*vb.y + vb.z*vb.z + vb.w*vb.w
                  + vc.x*vc.x + vc.y*vc.y + vc.z*vc.z + vc.w*vc.w;
#pragma unroll
        for (int o = 1; o < 16; o <<= 1)
            sv2 += __shfl_xor_sync(0xffffffffu, sv2, o);
        float vsc = rsqrtf(sv2 * (1.f / 64.f) + EPSLN);
#pragma unroll
        for (int s = 0; s < 4; s++) {
            int i0 = 4 * l + s, i1 = 64 + 4 * l + s, i2 = 128 + 4 * l + s;
            sV[(192 + i0) * ST + e] = ((const float*)&va)[s] * vsc * pGve[i0 / 3];
            sV[(192 + i1) * ST + e] = ((const float*)&vb)[s] * vsc * pGve[i1 / 3];
            sV[(192 + i2) * ST + e] = ((const float*)&vc)[s] * vsc * pGve[i2 / 3];
        }
    }
    __syncthreads();

    // ---- dotV = (V . sh1)/sqrt3 ; also zero sO0 for stage-2 reduction ----
    {
        const int e = t & 15;
        float shx = sSh[1 * ST + e], shy = sSh[2 * ST + e], shz = sSh[3 * ST + e];
#pragma unroll
        for (int it = 0; it < 8; it++) {
            int cc = (t >> 4) + 16 * it;
            sDot[cc * ST + e] =
                (sV[(cc * 3 + 0) * ST + e] * shx +
                 sV[(cc * 3 + 1) * ST + e] * shy +
                 sV[(cc * 3 + 2) * ST + e] * shz) * INV_SQ3;
        }
        for (int i = t; i < 192 * ST; i += 256) sO0[i] = 0.f;
    }
    __syncthreads();

    const ulonglong2* sS2  = (const ulonglong2*)sS;
    const ulonglong2* sD2  = (const ulonglong2*)sDot;
    const ulonglong2* sL2  = (const ulonglong2*)sLat;
    const ulonglong2* sV2  = (const ulonglong2*)sV;
    const ulonglong2* sO02 = (const ulonglong2*)sO0;
    const ulonglong2* sOV2 = (const ulonglong2*)sOV;

    // ---- Stage 2: out0 = sh0*(S@Wss0) + dot@Wvv0, k-split across groups ----
    {
        const int jj = t & 63, grp = t >> 6;
        u64 acc[3][8];
#pragma unroll
        for (int c = 0; c < 3; c++)
#pragma unroll
            for (int p = 0; p < 8; p++) acc[c][p] = 0;

        // S-part: k-quarter over all 16 edges
#pragma unroll 2
        for (int k = grp * 64; k < grp * 64 + 64; k++) {
            ulonglong2 q0 = sS2[k * NQ2 + 0], q1 = sS2[k * NQ2 + 1];
            ulonglong2 q2 = sS2[k * NQ2 + 2], q3 = sS2[k * NQ2 + 3];
            float4 w = w_ss0p[k * 64 + jj];
            u64 W0 = pk2(w.x), W1 = pk2(w.y), W2 = pk2(w.z);
            u64 A[8] = {q0.x, q0.y, q1.x, q1.y, q2.x, q2.y, q3.x, q3.y};
#pragma unroll
            for (int p = 0; p < 8; p++) {
                fma2(acc[0][p], A[p], W0);
                fma2(acc[1][p], A[p], W1);
                fma2(acc[2][p], A[p], W2);
            }
        }
        // scale S-part by sh0 per edge-pair
        {
            const ulonglong2* sh0q = (const ulonglong2*)&sSh[0];
            ulonglong2 s0 = sh0q[0], s1 = sh0q[1], s2 = sh0q[2], s3 = sh0q[3];
            u64 S[8] = {s0.x, s0.y, s1.x, s1.y, s2.x, s2.y, s3.x, s3.y};
#pragma unroll
            for (int c = 0; c < 3; c++)
#pragma unroll
                for (int p = 0; p < 8; p++) mul2(acc[c][p], S[p]);
        }
        // dot-part: k-quarter of Wvv0 accumulated on top
#pragma unroll 2
        for (int k = grp * 32; k < grp * 32 + 32; k++) {
            ulonglong2 q0 = sD2[k * NQ2 + 0], q1 = sD2[k * NQ2 + 1];
            ulonglong2 q2 = sD2[k * NQ2 + 2], q3 = sD2[k * NQ2 + 3];
            float4 w = w_vv0p[k * 64 + jj];
            u64 W0 = pk2(w.x), W1 = pk2(w.y), W2 = pk2(w.z);
            u64 A[8] = {q0.x, q0.y, q1.x, q1.y, q2.x, q2.y, q3.x, q3.y};
#pragma unroll
            for (int p = 0; p < 8; p++) {
                fma2(acc[0][p], A[p], W0);
                fma2(acc[1][p], A[p], W1);
                fma2(acc[2][p], A[p], W2);
            }
        }
        // atomic-reduce group partials into sO0 (spread addresses, conflict-free)
#pragma unroll
        for (int c = 0; c < 3; c++) {
            int col = jj + c * 64;
#pragma unroll
            for (int p = 0; p < 8; p++) {
                float2 v = up(acc[c][p]);
                atomicAdd(&sO0[col * ST + 2 * p],     v.x);
                atomicAdd(&sO0[col * ST + 2 * p + 1], v.y);
            }
        }
    }
    __syncthreads();

    // ---- Stage 3: t1 = S @ Wsv1 (quad k) ----
    {
        const int f = t & 63, egp = t >> 6;
        u64 acc[2] = {0, 0};
#pragma unroll 4
        for (int kk = 0; kk < 64; kk++) {
            float4 w = w_sv1q[kk * 64 + f];
            ulonglong2 a0 = sS2[(4 * kk + 0) * NQ2 + egp];
            ulonglong2 a1 = sS2[(4 * kk + 1) * NQ2 + egp];
            ulonglong2 a2 = sS2[(4 * kk + 2) * NQ2 + egp];
            ulonglong2 a3 = sS2[(4 * kk + 3) * NQ2 + egp];
            u64 W0 = pk2(w.x), W1 = pk2(w.y), W2 = pk2(w.z), W3 = pk2(w.w);
            fma2(acc[0], a0.x, W0); fma2(acc[1], a0.y, W0);
            fma2(acc[0], a1.x, W1); fma2(acc[1], a1.y, W1);
            fma2(acc[0], a2.x, W2); fma2(acc[1], a2.y, W2);
            fma2(acc[0], a3.x, W3); fma2(acc[1], a3.y, W3);
        }
        float r[4]; un4(acc, r);
        *(float4*)&sT1[f * ST + egp * 4] = make_float4(r[0], r[1], r[2], r[3]);
    }
    __syncthreads();

    // ---- Stage 4a: silu in place on rows 0..127 of sO0 ----
    {
        const int e = t & 15;
#pragma unroll
        for (int it = 0; it < 8; it++) {
            int j = (t >> 4) + 16 * it;
            float x = sO0[j * ST + e];
            sO0[j * ST + e] = x / (1.f + __expf(-x));
        }
    }
    // ---- Stage 4b: w = lat @ Wenv -> sS rows 0..191 ----
    {
        const int jj = t & 63, egp = t >> 6;
        u64 a0[2] = {0,0}, a1[2] = {0,0}, a2[2] = {0,0};
#pragma unroll 4
        for (int k = 0; k < 64; k++) {
            ulonglong2 a = sL2[k * NQ2 + egp];
            float4 w = w_envp[k * 64 + jj];
            u64 W0 = pk2(w.x), W1 = pk2(w.y), W2 = pk2(w.z);
            fma2(a0[0], a.x, W0); fma2(a0[1], a.y, W0);
            fma2(a1[0], a.x, W1); fma2(a1[1], a.y, W1);
            fma2(a2[0], a.x, W2); fma2(a2[1], a.y, W2);
        }
        __syncthreads();   // all reads of sS (stage 3) done before overwrite
        float r0[4], r1[4], r2[4];
        un4(a0, r0); un4(a1, r1); un4(a2, r2);
        *(float4*)&sS[jj * ST + egp * 4]         = make_float4(r0[0], r0[1], r0[2], r0[3]);
        *(float4*)&sS[(jj + 64) * ST + egp * 4]  = make_float4(r1[0], r1[1], r1[2], r1[3]);
        *(float4*)&sS[(jj + 128) * ST + egp * 4] = make_float4(r2[0], r2[1], r2[2], r2[3]);
    }
    // ---- Stage 4c: vector path (cross folded into epilogue, paired c) ----
    {
        const int f = t & 63, egp = t >> 6;
        u64 pAx[2]={0,0}, pAy[2]={0,0}, pAz[2]={0,0};
        u64 pBx[2]={0,0}, pBy[2]={0,0}, pBz[2]={0,0};
#pragma unroll 2
        for (int c2 = 0; c2 < 64; c2++) {
            float4 w = w_vsvvq[c2 * 64 + f];
            {
                int c = 2 * c2;
                ulonglong2 vx = sV2[(c * 3 + 0) * NQ2 + egp];
                ulonglong2 vy = sV2[(c * 3 + 1) * NQ2 + egp];
                ulonglong2 vz = sV2[(c * 3 + 2) * NQ2 + egp];
                u64 W1 = pk2(w.x), W2 = pk2(w.y);
                fma2(pAx[0], vx.x, W1); fma2(pAx[1], vx.y, W1);
                fma2(pAy[0], vy.x, W1); fma2(pAy[1], vy.y, W1);
                fma2(pAz[0], vz.x, W1); fma2(pAz[1], vz.y, W1);
                fma2(pBx[0], vx.x, W2); fma2(pBx[1], vx.y, W2);
                fma2(pBy[0], vy.x, W2); fma2(pBy[1], vy.y, W2);
                fma2(pBz[0], vz.x, W2); fma2(pBz[1], vz.y, W2);
            }
            {
                int c = 2 * c2 + 1;
                ulonglong2 vx = sV2[(c * 3 + 0) * NQ2 + egp];
                ulonglong2 vy = sV2[(c * 3 + 1) * NQ2 + egp];
                ulonglong2 vz = sV2[(c * 3 + 2) * NQ2 + egp];
                u64 W1 = pk2(w.z), W2 = pk2(w.w);
                fma2(pAx[0], vx.x, W1); fma2(pAx[1], vx.y, W1);
                fma2(pAy[0], vy.x, W1); fma2(pAy[1], vy.y, W1);
                fma2(pAz[0], vz.x, W1); fma2(pAz[1], vz.y, W1);
                fma2(pBx[0], vx.x, W2); fma2(pBx[1], vx.y, W2);
                fma2(pBy[0], vy.x, W2); fma2(pBy[1], vy.y, W2);
                fma2(pBz[0], vz.x, W2); fma2(pBz[1], vz.y, W2);
            }
        }
        float Ax[4], Ay[4], Az[4], Bx[4], By[4], Bz[4];
        un4(pAx, Ax); un4(pAy, Ay); un4(pAz, Az);
        un4(pBx, Bx); un4(pBy, By); un4(pBz, Bz);
        float4 s0 = *(const float4*)&sSh[0 * ST + egp * 4];
        float4 sx = *(const float4*)&sSh[1 * ST + egp * 4];
        float4 sy = *(const float4*)&sSh[2 * ST + egp * 4];
        float4 sz = *(const float4*)&sSh[3 * ST + egp * 4];
        float4 t1 = *(const float4*)&sT1[f * ST + egp * 4];
        float4 gg = *(const float4*)&sO0[(128 + f) * ST + egp * 4];
        float4 ox, oy, oz;
#pragma unroll
        for (int s = 0; s < 4; s++) {
            float g = 1.f / (1.f + __expf(-((const float*)&gg)[s]));
            float cx = (By[s] * ((const float*)&sz)[s] - Bz[s] * ((const float*)&sy)[s]) * INV_SQ2;
            float cy = (Bz[s] * ((const float*)&sx)[s] - Bx[s] * ((const float*)&sz)[s]) * INV_SQ2;
            float cz = (Bx[s] * ((const float*)&sy)[s] - By[s] * ((const float*)&sx)[s]) * INV_SQ2;
            float t1v = ((const float*)&t1)[s];
            float s0v = ((const float*)&s0)[s];
            ((float*)&ox)[s] = g * (s0v * Ax[s] + cx + t1v * ((const float*)&sx)[s]);
            ((float*)&oy)[s] = g * (s0v * Ay[s] + cy + t1v * ((const float*)&sy)[s]);
            ((float*)&oz)[s] = g * (s0v * Az[s] + cz + t1v * ((const float*)&sz)[s]);
        }
        *(float4*)&sOV[(f * 3 + 0) * ST + egp * 4] = ox;
        *(float4*)&sOV[(f * 3 + 1) * ST + egp * 4] = oy;
        *(float4*)&sOV[(f * 3 + 2) * ST + egp * 4] = oz;
    }
    __syncthreads();

    // ---- Stage 5a: s_out = (silu_s @ Wp_s) * w[:128], scatter (paired k) ----
    {
        const int jj = t & 63, egp = t >> 6;
        u64 a0[2] = {0,0}, a1[2] = {0,0};
#pragma unroll 4
        for (int k2 = 0; k2 < 64; k2++) {
            float4 w = w_psq[k2 * 64 + jj];
            ulonglong2 q0 = sO02[(2 * k2) * NQ2 + egp];
            ulonglong2 q1 = sO02[(2 * k2 + 1) * NQ2 + egp];
            u64 WA0 = pk2(w.x), WB0 = pk2(w.y), WA1 = pk2(w.z), WB1 = pk2(w.w);
            fma2(a0[0], q0.x, WA0); fma2(a0[1], q0.y, WA0);
            fma2(a1[0], q0.x, WB0); fma2(a1[1], q0.y, WB0);
            fma2(a0[0], q1.x, WA1); fma2(a0[1], q1.y, WA1);
            fma2(a1[0], q1.x, WB1); fma2(a1[1], q1.y, WB1);
        }
        float r0[4], r1[4];
        un4(a0, r0); un4(a1, r1);
        float4 w0 = *(const float4*)&sS[jj * ST + egp * 4];
        float4 w1 = *(const float4*)&sS[(jj + 64) * ST + egp * 4];
#pragma unroll
        for (int s = 0; s < 4; s++) {
            int c = sC[egp * 4 + s];
            atomicAdd(&out[c * 320 + jj],
                      r0[s] * ((const float*)&w0)[s] * 0.25f);
            atomicAdd(&out[c * 320 + 64 + jj],
                      r1[s] * ((const float*)&w1)[s] * 0.25f);
        }
    }
    // ---- Stage 5b: v_out = (v @ Wp_v) * w[128+f2], scatter (quad kf) ----
    {
        const int f2 = t & 63, egp = t >> 6;
        u64 pVx[2]={0,0}, pVy[2]={0,0}, pVz[2]={0,0};
#pragma unroll 2
        for (int kk = 0; kk < 16; kk++) {
            float4 w = w_pvq[kk * 64 + f2];
#pragma unroll
            for (int s = 0; s < 4; s++) {
                int kf = 4 * kk + s;
                u64 W = pk2(((const float*)&w)[s]);
                ulonglong2 vx = sOV2[(kf * 3 + 0) * NQ2 + egp];
                ulonglong2 vy = sOV2[(kf * 3 + 1) * NQ2 + egp];
                ulonglong2 vz = sOV2[(kf * 3 + 2) * NQ2 + egp];
                fma2(pVx[0], vx.x, W); fma2(pVx[1], vx.y, W);
                fma2(pVy[0], vy.x, W); fma2(pVy[1], vy.y, W);
                fma2(pVz[0], vz.x, W); fma2(pVz[1], vz.y, W);
            }
        }
        float Vx[4], Vy[4], Vz[4];
        un4(pVx, Vx); un4(pVy, Vy); un4(pVz, Vz);
        float4 wv = *(const float4*)&sS[(128 + f2) * ST + egp * 4];
#pragma unroll
        for (int s = 0; s < 4; s++) {
            int c = sC[egp * 4 + s];
            float ww = ((const float*)&wv)[s] * 0.25f;
            atomicAdd(&out[c * 320 + 128 + f2 * 3 + 0], Vx[s] * ww);
            atomicAdd(&out[c * 320 + 128 + f2 * 3 + 1], Vy[s] * ww);
            atomicAdd(&out[c * 320 + 128 + f2 * 3 + 2], Vz[s] * ww);
        }
    }
}

extern "C" void kernel_launch(void* const* d_in, const int* in_sizes, int n_in,
                              void* d_out, int out_size)
{
    const float* latents = (const float*)d_in[0];
    const float* nodef   = (const float*)d_in[1];
    const float* edgef   = (const float*)d_in[2];
    const float* esh     = (const float*)d_in[3];
    const int*   eidx    = (const int*)d_in[4];
    /* d_in[5] atom_type unused */
    const int*   act     = (const int*)d_in[6];
    const float* gsn  = (const float*)d_in[7];
    const float* bsn  = (const float*)d_in[8];
    const float* gvn  = (const float*)d_in[9];
    const float* gse  = (const float*)d_in[10];
    const float* bse  = (const float*)d_in[11];
    const float* gve  = (const float*)d_in[12];
    const float* Wss0 = (const float*)d_in[13];
    const float* Wvv0 = (const float*)d_in[14];
    const float* Wsv1 = (const float*)d_in[15];
    const float* Wvs1 = (const float*)d_in[16];
    const float* Wvv1 = (const float*)d_in[17];
    const float* Wps  = (const float*)d_in[18];
    const float* Wpv  = (const float*)d_in[19];
    const float* Wenv = (const float*)d_in[20];
    const float* Wrs  = (const float*)d_in[21];
    const float* Wrv  = (const float*)d_in[22];
    float* out = (float*)d_out;

    const size_t NODE_SMEM = (16384 + 4096 + 320 + 8) * sizeof(float);
    const size_t EDGE_SMEM = SMEM_EDGE_FLOATS * sizeof(float);

    cudaFuncSetAttribute(node_kernel, cudaFuncAttributeMaxDynamicSharedMemorySize,
                         (int)NODE_SMEM);
    cudaFuncSetAttribute(edge_kernel, cudaFuncAttributeMaxDynamicSharedMemorySize,
                         (int)EDGE_SMEM);

    prep_kernel<<<64, 256>>>(Wss0, Wvv0, Wenv, Wps, Wvs1, Wvv1, Wsv1, Wpv);
    node_kernel<<<296, 128, NODE_SMEM>>>(nodef, gsn, bsn, gvn, Wrs, Wrv, out);
    edge_kernel<<<10000, 256, EDGE_SMEM>>>(latents, edgef, esh, eidx, act,
                                           gse, bse, gve, out);
}